// round 11
// baseline (speedup 1.0000x reference)
#include <cuda_runtime.h>
#include <cuda_bf16.h>
#include <cstdint>
#include <cmath>

// ---------------------------------------------------------------------------
// Shapes: n1 = n2 = 4096, s = 192, a = 64, d = 256. Split-GEMM K = 768.
// ---------------------------------------------------------------------------
#define N      4096
#define DIM    256
#define SDIM   192
#define ADIM   64
#define KSPLIT 768
#define EPS    1e-8f

// ---------------------------------------------------------------------------
// Scratch (device globals — allocations forbidden)
// ---------------------------------------------------------------------------
__device__ __align__(256) float g_sa [N * DIM];
__device__ __align__(256) float g_esa[N * DIM];
__device__ __align__(256) float g_x2 [N];
__device__ __align__(256) float g_y2 [N];
__device__ __align__(256) float g_D  [(size_t)N * N];        // 64 MB
__device__ __align__(256) float g_D2 [DIM * DIM];
__device__ __align__(256) float g_D2p[16 * DIM * DIM];       // K-split partials
__device__ __align__(256) float g_sim[N];
__device__ __align__(256) float g_selfpart [(size_t)N * 128]; // row-sum slots
__device__ __align__(256) float g_selfpart2[(size_t)N * 64];  // col-sum slots
__device__ __align__(256) __nv_bfloat16 g_P[(size_t)N * KSPLIT]; // sa  [hi|hi|lo]
__device__ __align__(256) __nv_bfloat16 g_Q[(size_t)N * KSPLIT]; // sa  [hi|lo|hi]
__device__ __align__(256) __nv_bfloat16 g_R[(size_t)N * KSPLIT]; // esa [hi|lo|hi]
__device__ unsigned g_hist8 [256];     // fused pass-0 histogram (prep zeroes)
__device__ unsigned g_hist16[65536];   // 16-bit mid histogram   (prep zeroes)
__device__ unsigned g_histL [256];     // last-byte histogram    (prep zeroes)
__device__ unsigned g_selp;            // 24-bit prefix after mid pass
__device__ unsigned g_selk;            // remaining rank after mid pass
__device__ float    g_median[2];
__device__ float    g_gamma[2];

#define K_TARGET 8388607u   // (N*N - 1) / 2

// ---------------------------------------------------------------------------
// helpers
// ---------------------------------------------------------------------------
__device__ __forceinline__ uint32_t smem_u32(const void* p) {
    uint32_t a;
    asm("{ .reg .u64 t; cvta.to.shared.u64 t, %1; cvt.u32.u64 %0, t; }"
        : "=r"(a) : "l"(p));
    return a;
}
#define SW128B(o) ((o) ^ (((o) >> 3) & 0x70))

__device__ __forceinline__ void cp_async16(uint32_t sdst, const void* gsrc) {
    asm volatile("cp.async.cg.shared.global [%0], [%1], 16;"
                 :: "r"(sdst), "l"(gsrc) : "memory");
}
__device__ __forceinline__ void cp_commit() {
    asm volatile("cp.async.commit_group;" ::: "memory");
}
__device__ __forceinline__ void ldmx4(uint32_t& r0, uint32_t& r1,
                                      uint32_t& r2, uint32_t& r3, uint32_t addr) {
    asm volatile("ldmatrix.sync.aligned.m8n8.x4.shared.b16 {%0,%1,%2,%3}, [%4];"
                 : "=r"(r0), "=r"(r1), "=r"(r2), "=r"(r3) : "r"(addr));
}
__device__ __forceinline__ void mma_bf16(float& c0, float& c1, float& c2, float& c3,
                                         uint32_t a0, uint32_t a1, uint32_t a2, uint32_t a3,
                                         uint32_t b0, uint32_t b1) {
    asm volatile(
        "mma.sync.aligned.m16n8k16.row.col.f32.bf16.bf16.f32 "
        "{%0,%1,%2,%3}, {%4,%5,%6,%7}, {%8,%9}, {%0,%1,%2,%3};"
        : "+f"(c0), "+f"(c1), "+f"(c2), "+f"(c3)
        : "r"(a0), "r"(a1), "r"(a2), "r"(a3), "r"(b0), "r"(b1));
}
__device__ __forceinline__ unsigned f2u_mono(float f) {
    unsigned b = __float_as_uint(f);
    return (b & 0x80000000u) ? ~b : (b | 0x80000000u);
}

// ---------------------------------------------------------------------------
// 1) concat + norm + bf16 hi/lo splits, fused. Also zeroes select buffers.
// ---------------------------------------------------------------------------
__global__ void prep_kernel(const float* __restrict__ st,
                            const float* __restrict__ ac,
                            float* __restrict__ cat, float* __restrict__ nrm,
                            __nv_bfloat16* __restrict__ dst0, int phl0,
                            __nv_bfloat16* __restrict__ dst1) {
    int row = blockIdx.x, t = threadIdx.x;
    if (blockIdx.x < 256) g_hist16[blockIdx.x * 256 + t] = 0u;
    if (blockIdx.x == 256) g_hist8[t] = 0u;
    if (blockIdx.x == 257) g_histL[t] = 0u;
    float v = (t < SDIM) ? st[row * SDIM + t] : ac[row * ADIM + (t - SDIM)];
    cat[row * DIM + t] = v;
    __nv_bfloat16 hi = __float2bfloat16(v);
    __nv_bfloat16 lo = __float2bfloat16(v - __bfloat162float(hi));
    size_t base = (size_t)row * KSPLIT + t;
    dst0[base]       = hi;
    dst0[base + 256] = phl0 ? hi : lo;
    dst0[base + 512] = phl0 ? lo : hi;
    if (dst1) { dst1[base] = hi; dst1[base + 256] = lo; dst1[base + 512] = hi; }

    __shared__ float sh[256];
    sh[t] = v * v;
    __syncthreads();
    #pragma unroll
    for (int s = 128; s > 0; s >>= 1) {
        if (t < s) sh[t] += sh[t + s];
        __syncthreads();
    }
    if (t == 0) nrm[row] = sh[0];
}

// ---------------------------------------------------------------------------
// 2) HMMA distance GEMM — 128x128 CTA tile, 8 warps (2x4) of 64x32, BK=64,
//    3-stage cp.async pipeline, SW128 smem, K = 768, 2 CTAs/SM.
//    MODE 0: full grid; store D + fused MSB histogram -> g_hist8.
//    MODE 1: triangular grid (528 tiles); fused self row+col exp-sums, no D.
// ---------------------------------------------------------------------------
#define BK        64
#define TILE_B    (128 * BK * 2)
#define STG       (2 * TILE_B)
#define GM_SMEM   (3 * STG)               // 96 KB
#define NCHUNK    12
#define NTILE     32
#define NTRI      (NTILE * (NTILE + 1) / 2)

__device__ __forceinline__ void gemm_issue_stage(
    const __nv_bfloat16* __restrict__ A, const __nv_bfloat16* __restrict__ B,
    int i0, int j0, int c, uint32_t sA, uint32_t sB, int tid)
{
    const __nv_bfloat16* Ap = A + (size_t)i0 * KSPLIT + c * BK;
    const __nv_bfloat16* Bp = B + (size_t)j0 * KSPLIT + c * BK;
    #pragma unroll
    for (int q = 0; q < 4; q++) {
        int idx = tid + q * 256;
        int row = idx >> 3, seg = idx & 7;
        cp_async16(sA + SW128B(row * 128 + seg * 16),
                   Ap + (size_t)row * KSPLIT + seg * 8);
    }
    #pragma unroll
    for (int q = 0; q < 4; q++) {
        int idx = tid + q * 256;
        int row = idx >> 3, seg = idx & 7;
        cp_async16(sB + SW128B(row * 128 + seg * 16),
                   Bp + (size_t)row * KSPLIT + seg * 8);
    }
    cp_commit();
}

template <int MODE>
__global__ __launch_bounds__(256, 2)
void hmma_dist_gemm(const __nv_bfloat16* __restrict__ A,
                    const __nv_bfloat16* __restrict__ B,
                    const float* __restrict__ x2,
                    const float* __restrict__ y2,
                    float* __restrict__ D)
{
    extern __shared__ char smem[];
    const uint32_t sb = smem_u32(smem);
    const int tid = threadIdx.x;
    const int wid = tid >> 5, lane = tid & 31;
    const int warp_m = wid >> 2, warp_n = wid & 3;

    int ti, tj;
    if (MODE == 1) {
        int bid = blockIdx.x;
        ti = (int)(32.5f - sqrtf(32.5f * 32.5f - 2.0f * (float)bid));
        while (NTILE * ti - ti * (ti - 1) / 2 > bid) ti--;
        while (NTILE * (ti + 1) - (ti + 1) * ti / 2 <= bid) ti++;
        tj = ti + (bid - (NTILE * ti - ti * (ti - 1) / 2));
    } else {
        ti = blockIdx.y;
        tj = blockIdx.x;
    }
    const int i0 = ti * 128;
    const int j0 = tj * 128;

    uint32_t sA[3] = { sb,           sb + STG,           sb + 2 * STG };
    uint32_t sB[3] = { sb + TILE_B,  sb + STG + TILE_B,  sb + 2 * STG + TILE_B };

    float acc[4][4][4];
    #pragma unroll
    for (int mi = 0; mi < 4; mi++)
        #pragma unroll
        for (int ni = 0; ni < 4; ni++)
            #pragma unroll
            for (int e = 0; e < 4; e++) acc[mi][ni][e] = 0.f;

    gemm_issue_stage(A, B, i0, j0, 0, sA[0], sB[0], tid);
    gemm_issue_stage(A, B, i0, j0, 1, sA[1], sB[1], tid);
    gemm_issue_stage(A, B, i0, j0, 2, sA[2], sB[2], tid);

    const int a_row = (lane & 15);
    const int a_col = (lane & 16) ? 8 : 0;
    const int b_row = (lane & 7) + ((lane & 16) >> 1);
    const int b_col = (lane & 8) ? 8 : 0;

    for (int c = 0; c < NCHUNK; c++) {
        if (c < 10)      asm volatile("cp.async.wait_group 2;" ::: "memory");
        else if (c < 11) asm volatile("cp.async.wait_group 1;" ::: "memory");
        else             asm volatile("cp.async.wait_group 0;" ::: "memory");
        __syncthreads();

        int buf = c % 3;
        uint32_t cA = sA[buf], cB = sB[buf];
        #pragma unroll
        for (int ks = 0; ks < BK / 16; ks++) {
            int k0 = ks * 16;
            uint32_t a[4][4], b[2][4];
            #pragma unroll
            for (int mi = 0; mi < 4; mi++) {
                int row = warp_m * 64 + mi * 16 + a_row;
                ldmx4(a[mi][0], a[mi][1], a[mi][2], a[mi][3],
                      cA + SW128B(row * 128 + (k0 + a_col) * 2));
            }
            #pragma unroll
            for (int nb = 0; nb < 2; nb++) {
                int row = warp_n * 32 + nb * 16 + b_row;
                ldmx4(b[nb][0], b[nb][1], b[nb][2], b[nb][3],
                      cB + SW128B(row * 128 + (k0 + b_col) * 2));
            }
            #pragma unroll
            for (int mi = 0; mi < 4; mi++)
                #pragma unroll
                for (int ni = 0; ni < 4; ni++)
                    mma_bf16(acc[mi][ni][0], acc[mi][ni][1],
                             acc[mi][ni][2], acc[mi][ni][3],
                             a[mi][0], a[mi][1], a[mi][2], a[mi][3],
                             b[ni >> 1][(ni & 1) * 2], b[ni >> 1][(ni & 1) * 2 + 1]);
        }
        __syncthreads();
        if (c + 3 < NCHUNK)
            gemm_issue_stage(A, B, i0, j0, c + 3, sA[buf], sB[buf], tid);
    }

    const int qrow = lane >> 2;
    const int qcol = (lane & 3) * 2;

    if (MODE == 0) {
        unsigned* hsh = (unsigned*)smem;
        hsh[tid] = 0u;
        __syncthreads();
        unsigned lastb = 0xFFFFFFFFu, cnt = 0;

        #pragma unroll
        for (int mi = 0; mi < 4; mi++) {
            int i_lo = i0 + warp_m * 64 + mi * 16 + qrow;
            int i_hi = i_lo + 8;
            float xlo = x2[i_lo], xhi = x2[i_hi];
            #pragma unroll
            for (int ni = 0; ni < 4; ni++) {
                int j = j0 + warp_n * 32 + ni * 8 + qcol;
                float yj0 = y2[j], yj1 = y2[j + 1];
                float2 vlo, vhi;
                vlo.x = (xlo + yj0 - 2.f * acc[mi][ni][0]) * 0.00390625f;
                vlo.y = (xlo + yj1 - 2.f * acc[mi][ni][1]) * 0.00390625f;
                vhi.x = (xhi + yj0 - 2.f * acc[mi][ni][2]) * 0.00390625f;
                vhi.y = (xhi + yj1 - 2.f * acc[mi][ni][3]) * 0.00390625f;
                *(float2*)(D + (size_t)i_lo * N + j) = vlo;
                *(float2*)(D + (size_t)i_hi * N + j) = vhi;
                float vs[4] = {vlo.x, vlo.y, vhi.x, vhi.y};
                #pragma unroll
                for (int e = 0; e < 4; e++) {
                    unsigned bk = f2u_mono(vs[e]) >> 24;
                    if (bk == lastb) cnt++;
                    else {
                        if (cnt) atomicAdd(&hsh[lastb], cnt);
                        lastb = bk; cnt = 1;
                    }
                }
            }
        }
        if (cnt) atomicAdd(&hsh[lastb], cnt);
        __syncthreads();
        if (hsh[tid]) atomicAdd(&g_hist8[tid], hsh[tid]);
    } else {
        float g1 = g_gamma[0], g2 = g_gamma[1];
        float csum[4][2];
        #pragma unroll
        for (int ni = 0; ni < 4; ni++) { csum[ni][0] = 0.f; csum[ni][1] = 0.f; }

        #pragma unroll
        for (int mi = 0; mi < 4; mi++) {
            int i_lo = i0 + warp_m * 64 + mi * 16 + qrow;
            int i_hi = i_lo + 8;
            float xlo = x2[i_lo], xhi = x2[i_hi];
            float slo = 0.f, shi = 0.f;
            #pragma unroll
            for (int ni = 0; ni < 4; ni++) {
                int j = j0 + warp_n * 32 + ni * 8 + qcol;
                float yj0 = y2[j], yj1 = y2[j + 1];
                float d0 = (xlo + yj0 - 2.f * acc[mi][ni][0]) * 0.00390625f;
                float d1 = (xlo + yj1 - 2.f * acc[mi][ni][1]) * 0.00390625f;
                float d2v = (xhi + yj0 - 2.f * acc[mi][ni][2]) * 0.00390625f;
                float d3 = (xhi + yj1 - 2.f * acc[mi][ni][3]) * 0.00390625f;
                float e0 = __expf(-g1 * d0)  + __expf(-g2 * d0);
                float e1 = __expf(-g1 * d1)  + __expf(-g2 * d1);
                float e2 = __expf(-g1 * d2v) + __expf(-g2 * d2v);
                float e3 = __expf(-g1 * d3)  + __expf(-g2 * d3);
                slo += e0 + e1;
                shi += e2 + e3;
                csum[ni][0] += e0 + e2;
                csum[ni][1] += e1 + e3;
            }
            slo += __shfl_xor_sync(0xFFFFFFFFu, slo, 1);
            slo += __shfl_xor_sync(0xFFFFFFFFu, slo, 2);
            shi += __shfl_xor_sync(0xFFFFFFFFu, shi, 1);
            shi += __shfl_xor_sync(0xFFFFFFFFu, shi, 2);
            if ((lane & 3) == 0) {
                int col = tj * 4 + warp_n;
                g_selfpart[(size_t)i_lo * 128 + col] = slo;
                g_selfpart[(size_t)i_hi * 128 + col] = shi;
            }
        }
        if (ti != tj) {
            #pragma unroll
            for (int ni = 0; ni < 4; ni++) {
                #pragma unroll
                for (int cc = 0; cc < 2; cc++) {
                    float v = csum[ni][cc];
                    v += __shfl_xor_sync(0xFFFFFFFFu, v, 4);
                    v += __shfl_xor_sync(0xFFFFFFFFu, v, 8);
                    v += __shfl_xor_sync(0xFFFFFFFFu, v, 16);
                    if (lane < 4) {
                        int j = j0 + warp_n * 32 + ni * 8 + lane * 2 + cc;
                        g_selfpart2[(size_t)j * 64 + ti * 2 + warp_m] = v;
                    }
                }
            }
        }
    }
}

// ---------------------------------------------------------------------------
// 3) gamma_2 Gram: 64x64 tiles, 4x4/thread via float4 LDS, symmetric tiles,
//    z = 16 K-slabs of 256. (c2 comes from the Gram diagonal in d2_final.)
// ---------------------------------------------------------------------------
__global__ __launch_bounds__(256)
void d2_part_kernel() {
    // upper-tri 64-tile pairs of a 4x4 grid: 10 pairs
    int p = blockIdx.x;
    int ti = 0, rem = p;
    while (rem >= 4 - ti) { rem -= 4 - ti; ti++; }
    int tj = ti + rem;
    const int i0 = ti * 64, j0 = tj * 64;
    const int k0 = blockIdx.y * 256;

    __shared__ float Ei[32][64];
    __shared__ float Ej[32][64];
    const int tid = threadIdx.x;
    const int tx = tid & 15, ty = tid >> 4;

    float acc[4][4] = {};

    for (int kc = k0; kc < k0 + 256; kc += 32) {
        #pragma unroll
        for (int q = 0; q < 2; q++) {
            int idx = tid + q * 256;        // 0..511
            int kk = idx >> 4, c4 = (idx & 15) * 4;
            *(float4*)&Ei[kk][c4] =
                *(const float4*)&g_esa[(size_t)(kc + kk) * DIM + i0 + c4];
            *(float4*)&Ej[kk][c4] =
                *(const float4*)&g_esa[(size_t)(kc + kk) * DIM + j0 + c4];
        }
        __syncthreads();
        #pragma unroll
        for (int kk = 0; kk < 32; kk++) {
            float4 a = *(float4*)&Ei[kk][ty * 4];
            float4 b = *(float4*)&Ej[kk][tx * 4];
            acc[0][0] += a.x * b.x; acc[0][1] += a.x * b.y;
            acc[0][2] += a.x * b.z; acc[0][3] += a.x * b.w;
            acc[1][0] += a.y * b.x; acc[1][1] += a.y * b.y;
            acc[1][2] += a.y * b.z; acc[1][3] += a.y * b.w;
            acc[2][0] += a.z * b.x; acc[2][1] += a.z * b.y;
            acc[2][2] += a.z * b.z; acc[2][3] += a.z * b.w;
            acc[3][0] += a.w * b.x; acc[3][1] += a.w * b.y;
            acc[3][2] += a.w * b.z; acc[3][3] += a.w * b.w;
        }
        __syncthreads();
    }

    float* P = g_D2p + (size_t)blockIdx.y * DIM * DIM;
    #pragma unroll
    for (int r = 0; r < 4; r++) {
        #pragma unroll
        for (int c = 0; c < 4; c++)
            P[(size_t)(i0 + ty * 4 + r) * DIM + j0 + tx * 4 + c] = acc[r][c];
    }
}

__global__ void d2_final_kernel() {
    int i = blockIdx.x, t = threadIdx.x;
    __shared__ float diag[256];
    float dsum = 0.f;
    #pragma unroll
    for (int z = 0; z < 16; z++)
        dsum += g_D2p[(size_t)z * DIM * DIM + t * DIM + t];
    diag[t] = dsum;
    // symmetric partial read: upper-tri (64-wide tiles) holds the data
    size_t idx = ((i >> 6) <= (t >> 6)) ? (size_t)i * DIM + t
                                        : (size_t)t * DIM + i;
    float s = 0.f;
    #pragma unroll
    for (int z = 0; z < 16; z++)
        s += g_D2p[(size_t)z * DIM * DIM + idx];
    __syncthreads();
    g_D2[i * DIM + t] = (diag[i] + diag[t] - 2.f * s) * (1.f / 4096.f);
}

// ---------------------------------------------------------------------------
// 4a) D2 median + gamma_2: one single-block kernel (all 4 radix passes)
// ---------------------------------------------------------------------------
__global__ __launch_bounds__(1024)
void d2_median_kernel() {
    __shared__ unsigned hist[256];
    __shared__ unsigned s[256];
    __shared__ unsigned sh_prefix, sh_k;
    int t = threadIdx.x;
    if (t == 0) { sh_prefix = 0u; sh_k = (DIM * DIM - 1) / 2; }
    __syncthreads();
    #pragma unroll
    for (int pass = 0; pass < 4; pass++) {
        if (t < 256) hist[t] = 0u;
        __syncthreads();
        int shift = 24 - pass * 8;
        unsigned prefix = sh_prefix;
        for (int i = t; i < DIM * DIM; i += 1024) {
            unsigned u = f2u_mono(g_D2[i]);
            bool ok = (pass == 0) || ((u >> (shift + 8)) == prefix);
            if (ok) atomicAdd(&hist[(u >> shift) & 0xFFu], 1u);
        }
        __syncthreads();
        unsigned kcur = sh_k;
        if (t < 256) s[t] = hist[t];
        __syncthreads();
        for (int off = 1; off < 256; off <<= 1) {
            unsigned v = (t < 256 && t >= off) ? s[t - off] : 0u;
            __syncthreads();
            if (t < 256) s[t] += v;
            __syncthreads();
        }
        if (t < 256) {
            unsigned c = hist[t];
            unsigned incl = s[t], excl = incl - c;
            if (kcur >= excl && kcur < incl) {
                sh_k = kcur - excl;
                sh_prefix = (prefix << 8) | (unsigned)t;
            }
        }
        __syncthreads();
    }
    if (t == 0) {
        unsigned u = sh_prefix;
        unsigned bits = (u & 0x80000000u) ? (u ^ 0x80000000u) : ~u;
        g_median[1] = __uint_as_float(bits);
        g_gamma[1]  = 1.0f / (__uint_as_float(bits) + EPS);
    }
}

// ---------------------------------------------------------------------------
// 4b) D median, two-level:
//     pass 0 (8-bit) fused in GEMM1 -> g_hist8
//     mid pass: 16-bit histogram of matching elements -> g_hist16
//     select_mid: pick 16-bit bucket -> g_selp (24-bit prefix), g_selk
//     last pass: final byte histogram -> g_histL; finalize -> gamma_1
// ---------------------------------------------------------------------------
__device__ __forceinline__ void prefix8_from_hist(unsigned& prefix_out,
                                                  unsigned& k_out,
                                                  unsigned* s) {
    int t = threadIdx.x;
    unsigned c = g_hist8[t];
    s[t] = c;
    __syncthreads();
    for (int off = 1; off < 256; off <<= 1) {
        unsigned v = (t >= off) ? s[t - off] : 0u;
        __syncthreads();
        s[t] += v;
        __syncthreads();
    }
    __shared__ unsigned sh2[2];
    unsigned incl = s[t], excl = incl - c;
    if (K_TARGET >= excl && K_TARGET < incl) {
        sh2[0] = (unsigned)t;
        sh2[1] = K_TARGET - excl;
    }
    __syncthreads();
    prefix_out = sh2[0];
    k_out = sh2[1];
}

__global__ __launch_bounds__(256)
void select_hist16_kernel(const float* __restrict__ data, unsigned n4) {
    __shared__ unsigned s[256];
    unsigned prefix8, kdummy;
    prefix8_from_hist(prefix8, kdummy, s);

    unsigned stride = gridDim.x * blockDim.x;
    int lane = threadIdx.x & 31;
    const float4* d4 = (const float4*)data;
    for (unsigned base = blockIdx.x * blockDim.x; base < n4; base += stride) {
        unsigned i = base + threadIdx.x;
        float4 v = make_float4(0.f, 0.f, 0.f, 0.f);
        bool valid = (i < n4);
        if (valid) v = d4[i];
        float vals[4] = {v.x, v.y, v.z, v.w};
        #pragma unroll
        for (int e = 0; e < 4; e++) {
            unsigned bucket = 0xFFFFFFFFu;
            if (valid) {
                unsigned u = f2u_mono(vals[e]);
                if ((u >> 24) == prefix8) bucket = (u >> 8) & 0xFFFFu;
            }
            unsigned m = __match_any_sync(0xFFFFFFFFu, bucket);
            if (bucket != 0xFFFFFFFFu && lane == __ffs(m) - 1)
                atomicAdd(&g_hist16[bucket], (unsigned)__popc(m));
        }
    }
}

__global__ __launch_bounds__(256)
void select_mid_kernel() {
    __shared__ unsigned s[256];
    unsigned prefix8, k8;
    prefix8_from_hist(prefix8, k8, s);
    __syncthreads();

    int t = threadIdx.x;
    unsigned mysum = 0;
    int base = t * 256;
    for (int i = 0; i < 256; i++) mysum += g_hist16[base + i];
    s[t] = mysum;
    __syncthreads();
    for (int off = 1; off < 256; off <<= 1) {
        unsigned v = (t >= off) ? s[t - off] : 0u;
        __syncthreads();
        s[t] += v;
        __syncthreads();
    }
    unsigned incl = s[t], excl = incl - mysum;
    if (k8 >= excl && k8 < incl) {
        unsigned k = k8 - excl;
        for (int i = 0; i < 256; i++) {
            unsigned c = g_hist16[base + i];
            if (k < c) {
                g_selp = (prefix8 << 16) | (unsigned)(base + i);
                g_selk = k;
                break;
            }
            k -= c;
        }
    }
}

__global__ __launch_bounds__(256)
void select_histL_kernel(const float* __restrict__ data, unsigned n4) {
    __shared__ unsigned hloc[256];
    hloc[threadIdx.x] = 0u;
    __syncthreads();
    unsigned prefix24 = g_selp;
    unsigned stride = gridDim.x * blockDim.x;
    int lane = threadIdx.x & 31;
    const float4* d4 = (const float4*)data;
    for (unsigned base = blockIdx.x * blockDim.x; base < n4; base += stride) {
        unsigned i = base + threadIdx.x;
        float4 v = make_float4(0.f, 0.f, 0.f, 0.f);
        bool valid = (i < n4);
        if (valid) v = d4[i];
        float vals[4] = {v.x, v.y, v.z, v.w};
        #pragma unroll
        for (int e = 0; e < 4; e++) {
            unsigned bucket = 0xFFFFFFFFu;
            if (valid) {
                unsigned u = f2u_mono(vals[e]);
                if ((u >> 8) == prefix24) bucket = u & 0xFFu;
            }
            unsigned m = __match_any_sync(0xFFFFFFFFu, bucket);
            if (bucket != 0xFFFFFFFFu && lane == __ffs(m) - 1)
                atomicAdd(&hloc[bucket], (unsigned)__popc(m));
        }
    }
    __syncthreads();
    if (hloc[threadIdx.x]) atomicAdd(&g_histL[threadIdx.x], hloc[threadIdx.x]);
}

__global__ __launch_bounds__(256)
void select_fin_kernel() {
    __shared__ unsigned s[256];
    int t = threadIdx.x;
    unsigned c = g_histL[t];
    s[t] = c;
    __syncthreads();
    for (int off = 1; off < 256; off <<= 1) {
        unsigned v = (t >= off) ? s[t - off] : 0u;
        __syncthreads();
        s[t] += v;
        __syncthreads();
    }
    unsigned k = g_selk;
    unsigned incl = s[t], excl = incl - c;
    if (k >= excl && k < incl) {
        unsigned prefix = (g_selp << 8) | (unsigned)t;
        unsigned bits = (prefix & 0x80000000u) ? (prefix ^ 0x80000000u) : ~prefix;
        g_median[0] = __uint_as_float(bits);
        g_gamma[0]  = 1.0f / (__uint_as_float(bits) + EPS);
    }
}

// ---------------------------------------------------------------------------
// 5) Row means of exp over stored D (agent-expert pass)
// ---------------------------------------------------------------------------
__global__ __launch_bounds__(256)
void rowsum_kernel(const float* __restrict__ D) {
    int i = blockIdx.x, t = threadIdx.x;
    float g1 = g_gamma[0], g2 = g_gamma[1];
    const float4* row = (const float4*)(D + (size_t)i * N);
    float s = 0.f;
    #pragma unroll 4
    for (int j = t; j < N / 4; j += 256) {
        float4 v = row[j];
        s += __expf(-g1 * v.x) + __expf(-g1 * v.y) + __expf(-g1 * v.z) + __expf(-g1 * v.w)
           + __expf(-g2 * v.x) + __expf(-g2 * v.y) + __expf(-g2 * v.z) + __expf(-g2 * v.w);
    }
    __shared__ float sh[256];
    sh[t] = s;
    __syncthreads();
    #pragma unroll
    for (int k = 128; k > 0; k >>= 1) {
        if (t < k) sh[t] += sh[t + k];
        __syncthreads();
    }
    if (t == 0) g_sim[i] = sh[0] * (1.0f / (float)N);
}

// ---------------------------------------------------------------------------
// 6) final: out[i] = g_sim[i] - mean of valid self partials
// ---------------------------------------------------------------------------
__global__ void self_final_kernel(float* __restrict__ out) {
    int i = blockIdx.x * blockDim.x + threadIdx.x;
    int t = i >> 7;
    const float* rp = g_selfpart  + (size_t)i * 128;
    const float* cp = g_selfpart2 + (size_t)i * 64;
    float s = 0.f;
    for (int b = 4 * t; b < 128; b++) s += rp[b];
    for (int b = 0; b < 2 * t; b++)  s += cp[b];
    out[i] = g_sim[i] - s * (1.0f / (float)N);
}

// ---------------------------------------------------------------------------
// Host orchestration (graph-capturable)
// ---------------------------------------------------------------------------
extern "C" void kernel_launch(void* const* d_in, const int* in_sizes, int n_in,
                              void* d_out, int out_size) {
    const float* state   = (const float*)d_in[0];
    const float* action  = (const float*)d_in[1];
    const float* estate  = (const float*)d_in[2];
    const float* eaction = (const float*)d_in[3];
    float* out = (float*)d_out;

    float *p_sa, *p_esa, *p_x2, *p_y2, *p_D;
    __nv_bfloat16 *p_P, *p_Q, *p_R;
    cudaGetSymbolAddress((void**)&p_sa,  g_sa);
    cudaGetSymbolAddress((void**)&p_esa, g_esa);
    cudaGetSymbolAddress((void**)&p_x2,  g_x2);
    cudaGetSymbolAddress((void**)&p_y2,  g_y2);
    cudaGetSymbolAddress((void**)&p_D,   g_D);
    cudaGetSymbolAddress((void**)&p_P,   g_P);
    cudaGetSymbolAddress((void**)&p_Q,   g_Q);
    cudaGetSymbolAddress((void**)&p_R,   g_R);

    cudaFuncSetAttribute(hmma_dist_gemm<0>,
                         cudaFuncAttributeMaxDynamicSharedMemorySize, GM_SMEM);
    cudaFuncSetAttribute(hmma_dist_gemm<1>,
                         cudaFuncAttributeMaxDynamicSharedMemorySize, GM_SMEM);

    // 1) concat + norms + bf16 splits (also zeroes select histograms)
    prep_kernel<<<N, 256>>>(state,  action,  p_sa,  p_x2, p_P, 1, p_Q);
    prep_kernel<<<N, 256>>>(estate, eaction, p_esa, p_y2, p_R, 0, nullptr);

    // 2) D_agent_expert + fused MSB histogram -> g_hist8
    dim3 ggrid(N / 128, N / 128);
    hmma_dist_gemm<0><<<ggrid, 256, GM_SMEM>>>(p_P, p_R, p_x2, p_y2, p_D);

    // 3) gamma_2 matrix + single-launch median
    d2_part_kernel<<<dim3(10, 16), 256>>>();
    d2_final_kernel<<<DIM, DIM>>>();
    d2_median_kernel<<<1, 1024>>>();

    // 4) D median: 16-bit mid pass + final byte pass
    {
        unsigned n4 = ((unsigned)N * (unsigned)N) / 4u;
        select_hist16_kernel<<<2048, 256>>>(p_D, n4);
        select_mid_kernel<<<1, 256>>>();
        select_histL_kernel<<<2048, 256>>>(p_D, n4);
        select_fin_kernel<<<1, 256>>>();
    }

    // 5) agent-expert similarity means from stored D
    rowsum_kernel<<<N, 256>>>(p_D);

    // 6) self-distance GEMM, triangular, fused row+col sums
    hmma_dist_gemm<1><<<NTRI, 256, GM_SMEM>>>(p_P, p_Q, p_x2, p_x2, nullptr);
    self_final_kernel<<<N / 256, 256>>>(out);
}

// round 12
// speedup vs baseline: 1.2002x; 1.2002x over previous
#include <cuda_runtime.h>
#include <cuda_bf16.h>
#include <cstdint>
#include <cmath>

// ---------------------------------------------------------------------------
// Shapes: n1 = n2 = 4096, s = 192, a = 64, d = 256. Split-GEMM K = 768.
// ---------------------------------------------------------------------------
#define N      4096
#define DIM    256
#define SDIM   192
#define ADIM   64
#define KSPLIT 768
#define EPS    1e-8f
#define NSLAB  32

// ---------------------------------------------------------------------------
// Scratch (device globals — allocations forbidden)
// ---------------------------------------------------------------------------
__device__ __align__(256) float g_sa [N * DIM];
__device__ __align__(256) float g_esa[N * DIM];
__device__ __align__(256) float g_x2 [N];
__device__ __align__(256) float g_y2 [N];
__device__ __align__(256) float g_D  [(size_t)N * N];        // 64 MB
__device__ __align__(256) float g_D2 [DIM * DIM];
__device__ __align__(256) float g_D2p[NSLAB * DIM * DIM];    // K-split partials
__device__ __align__(256) float g_sim[N];
__device__ __align__(256) float g_selfpart [(size_t)N * 128]; // row-sum slots
__device__ __align__(256) float g_selfpart2[(size_t)N * 64];  // col-sum slots
__device__ __align__(256) __nv_bfloat16 g_P[(size_t)N * KSPLIT]; // sa  [hi|hi|lo]
__device__ __align__(256) __nv_bfloat16 g_Q[(size_t)N * KSPLIT]; // sa  [hi|lo|hi]
__device__ __align__(256) __nv_bfloat16 g_R[(size_t)N * KSPLIT]; // esa [hi|lo|hi]
__device__ unsigned g_hist4[4 * 256];  // per-pass histograms (prep zeroes)
__device__ float    g_median[2];
__device__ float    g_gamma[2];

#define K_TARGET 8388607u   // (N*N - 1) / 2

// ---------------------------------------------------------------------------
// helpers
// ---------------------------------------------------------------------------
__device__ __forceinline__ uint32_t smem_u32(const void* p) {
    uint32_t a;
    asm("{ .reg .u64 t; cvta.to.shared.u64 t, %1; cvt.u32.u64 %0, t; }"
        : "=r"(a) : "l"(p));
    return a;
}
#define SW128B(o) ((o) ^ (((o) >> 3) & 0x70))

__device__ __forceinline__ void cp_async16(uint32_t sdst, const void* gsrc) {
    asm volatile("cp.async.cg.shared.global [%0], [%1], 16;"
                 :: "r"(sdst), "l"(gsrc) : "memory");
}
__device__ __forceinline__ void cp_commit() {
    asm volatile("cp.async.commit_group;" ::: "memory");
}
__device__ __forceinline__ void ldmx4(uint32_t& r0, uint32_t& r1,
                                      uint32_t& r2, uint32_t& r3, uint32_t addr) {
    asm volatile("ldmatrix.sync.aligned.m8n8.x4.shared.b16 {%0,%1,%2,%3}, [%4];"
                 : "=r"(r0), "=r"(r1), "=r"(r2), "=r"(r3) : "r"(addr));
}
__device__ __forceinline__ void mma_bf16(float& c0, float& c1, float& c2, float& c3,
                                         uint32_t a0, uint32_t a1, uint32_t a2, uint32_t a3,
                                         uint32_t b0, uint32_t b1) {
    asm volatile(
        "mma.sync.aligned.m16n8k16.row.col.f32.bf16.bf16.f32 "
        "{%0,%1,%2,%3}, {%4,%5,%6,%7}, {%8,%9}, {%0,%1,%2,%3};"
        : "+f"(c0), "+f"(c1), "+f"(c2), "+f"(c3)
        : "r"(a0), "r"(a1), "r"(a2), "r"(a3), "r"(b0), "r"(b1));
}
__device__ __forceinline__ unsigned f2u_mono(float f) {
    unsigned b = __float_as_uint(f);
    return (b & 0x80000000u) ? ~b : (b | 0x80000000u);
}

// ---------------------------------------------------------------------------
// 1) concat + norm + bf16 hi/lo splits, fused. Also zeroes g_hist4.
// ---------------------------------------------------------------------------
__global__ void prep_kernel(const float* __restrict__ st,
                            const float* __restrict__ ac,
                            float* __restrict__ cat, float* __restrict__ nrm,
                            __nv_bfloat16* __restrict__ dst0, int phl0,
                            __nv_bfloat16* __restrict__ dst1) {
    int row = blockIdx.x, t = threadIdx.x;
    if (blockIdx.x < 4) g_hist4[blockIdx.x * 256 + t] = 0u;
    float v = (t < SDIM) ? st[row * SDIM + t] : ac[row * ADIM + (t - SDIM)];
    cat[row * DIM + t] = v;
    __nv_bfloat16 hi = __float2bfloat16(v);
    __nv_bfloat16 lo = __float2bfloat16(v - __bfloat162float(hi));
    size_t base = (size_t)row * KSPLIT + t;
    dst0[base]       = hi;
    dst0[base + 256] = phl0 ? hi : lo;
    dst0[base + 512] = phl0 ? lo : hi;
    if (dst1) { dst1[base] = hi; dst1[base + 256] = lo; dst1[base + 512] = hi; }

    __shared__ float sh[256];
    sh[t] = v * v;
    __syncthreads();
    #pragma unroll
    for (int s = 128; s > 0; s >>= 1) {
        if (t < s) sh[t] += sh[t + s];
        __syncthreads();
    }
    if (t == 0) nrm[row] = sh[0];
}

// ---------------------------------------------------------------------------
// 2) HMMA distance GEMM — 128x128 CTA tile, 8 warps (2x4) of 64x32, BK=64,
//    3-stage cp.async pipeline, SW128 smem, K = 768, 2 CTAs/SM.
//    MODE 0: full grid; store D + fused MSB histogram -> g_hist4[0].
//    MODE 1: triangular grid (528 tiles); fused self row+col exp-sums, no D.
// ---------------------------------------------------------------------------
#define BK        64
#define TILE_B    (128 * BK * 2)
#define STG       (2 * TILE_B)
#define GM_SMEM   (3 * STG)               // 96 KB
#define NCHUNK    12
#define NTILE     32
#define NTRI      (NTILE * (NTILE + 1) / 2)

__device__ __forceinline__ void gemm_issue_stage(
    const __nv_bfloat16* __restrict__ A, const __nv_bfloat16* __restrict__ B,
    int i0, int j0, int c, uint32_t sA, uint32_t sB, int tid)
{
    const __nv_bfloat16* Ap = A + (size_t)i0 * KSPLIT + c * BK;
    const __nv_bfloat16* Bp = B + (size_t)j0 * KSPLIT + c * BK;
    #pragma unroll
    for (int q = 0; q < 4; q++) {
        int idx = tid + q * 256;
        int row = idx >> 3, seg = idx & 7;
        cp_async16(sA + SW128B(row * 128 + seg * 16),
                   Ap + (size_t)row * KSPLIT + seg * 8);
    }
    #pragma unroll
    for (int q = 0; q < 4; q++) {
        int idx = tid + q * 256;
        int row = idx >> 3, seg = idx & 7;
        cp_async16(sB + SW128B(row * 128 + seg * 16),
                   Bp + (size_t)row * KSPLIT + seg * 8);
    }
    cp_commit();
}

template <int MODE>
__global__ __launch_bounds__(256, 2)
void hmma_dist_gemm(const __nv_bfloat16* __restrict__ A,
                    const __nv_bfloat16* __restrict__ B,
                    const float* __restrict__ x2,
                    const float* __restrict__ y2,
                    float* __restrict__ D)
{
    extern __shared__ char smem[];
    const uint32_t sb = smem_u32(smem);
    const int tid = threadIdx.x;
    const int wid = tid >> 5, lane = tid & 31;
    const int warp_m = wid >> 2, warp_n = wid & 3;

    int ti, tj;
    if (MODE == 1) {
        int bid = blockIdx.x;
        ti = (int)(32.5f - sqrtf(32.5f * 32.5f - 2.0f * (float)bid));
        while (NTILE * ti - ti * (ti - 1) / 2 > bid) ti--;
        while (NTILE * (ti + 1) - (ti + 1) * ti / 2 <= bid) ti++;
        tj = ti + (bid - (NTILE * ti - ti * (ti - 1) / 2));
    } else {
        ti = blockIdx.y;
        tj = blockIdx.x;
    }
    const int i0 = ti * 128;
    const int j0 = tj * 128;

    uint32_t sA[3] = { sb,           sb + STG,           sb + 2 * STG };
    uint32_t sB[3] = { sb + TILE_B,  sb + STG + TILE_B,  sb + 2 * STG + TILE_B };

    float acc[4][4][4];
    #pragma unroll
    for (int mi = 0; mi < 4; mi++)
        #pragma unroll
        for (int ni = 0; ni < 4; ni++)
            #pragma unroll
            for (int e = 0; e < 4; e++) acc[mi][ni][e] = 0.f;

    gemm_issue_stage(A, B, i0, j0, 0, sA[0], sB[0], tid);
    gemm_issue_stage(A, B, i0, j0, 1, sA[1], sB[1], tid);
    gemm_issue_stage(A, B, i0, j0, 2, sA[2], sB[2], tid);

    const int a_row = (lane & 15);
    const int a_col = (lane & 16) ? 8 : 0;
    const int b_row = (lane & 7) + ((lane & 16) >> 1);
    const int b_col = (lane & 8) ? 8 : 0;

    for (int c = 0; c < NCHUNK; c++) {
        if (c < 10)      asm volatile("cp.async.wait_group 2;" ::: "memory");
        else if (c < 11) asm volatile("cp.async.wait_group 1;" ::: "memory");
        else             asm volatile("cp.async.wait_group 0;" ::: "memory");
        __syncthreads();

        int buf = c % 3;
        uint32_t cA = sA[buf], cB = sB[buf];
        #pragma unroll
        for (int ks = 0; ks < BK / 16; ks++) {
            int k0 = ks * 16;
            uint32_t a[4][4], b[2][4];
            #pragma unroll
            for (int mi = 0; mi < 4; mi++) {
                int row = warp_m * 64 + mi * 16 + a_row;
                ldmx4(a[mi][0], a[mi][1], a[mi][2], a[mi][3],
                      cA + SW128B(row * 128 + (k0 + a_col) * 2));
            }
            #pragma unroll
            for (int nb = 0; nb < 2; nb++) {
                int row = warp_n * 32 + nb * 16 + b_row;
                ldmx4(b[nb][0], b[nb][1], b[nb][2], b[nb][3],
                      cB + SW128B(row * 128 + (k0 + b_col) * 2));
            }
            #pragma unroll
            for (int mi = 0; mi < 4; mi++)
                #pragma unroll
                for (int ni = 0; ni < 4; ni++)
                    mma_bf16(acc[mi][ni][0], acc[mi][ni][1],
                             acc[mi][ni][2], acc[mi][ni][3],
                             a[mi][0], a[mi][1], a[mi][2], a[mi][3],
                             b[ni >> 1][(ni & 1) * 2], b[ni >> 1][(ni & 1) * 2 + 1]);
        }
        __syncthreads();
        if (c + 3 < NCHUNK)
            gemm_issue_stage(A, B, i0, j0, c + 3, sA[buf], sB[buf], tid);
    }

    const int qrow = lane >> 2;
    const int qcol = (lane & 3) * 2;

    if (MODE == 0) {
        unsigned* hsh = (unsigned*)smem;
        hsh[tid] = 0u;
        __syncthreads();
        unsigned lastb = 0xFFFFFFFFu, cnt = 0;

        #pragma unroll
        for (int mi = 0; mi < 4; mi++) {
            int i_lo = i0 + warp_m * 64 + mi * 16 + qrow;
            int i_hi = i_lo + 8;
            float xlo = x2[i_lo], xhi = x2[i_hi];
            #pragma unroll
            for (int ni = 0; ni < 4; ni++) {
                int j = j0 + warp_n * 32 + ni * 8 + qcol;
                float yj0 = y2[j], yj1 = y2[j + 1];
                float2 vlo, vhi;
                vlo.x = (xlo + yj0 - 2.f * acc[mi][ni][0]) * 0.00390625f;
                vlo.y = (xlo + yj1 - 2.f * acc[mi][ni][1]) * 0.00390625f;
                vhi.x = (xhi + yj0 - 2.f * acc[mi][ni][2]) * 0.00390625f;
                vhi.y = (xhi + yj1 - 2.f * acc[mi][ni][3]) * 0.00390625f;
                *(float2*)(D + (size_t)i_lo * N + j) = vlo;
                *(float2*)(D + (size_t)i_hi * N + j) = vhi;
                float vs[4] = {vlo.x, vlo.y, vhi.x, vhi.y};
                #pragma unroll
                for (int e = 0; e < 4; e++) {
                    unsigned bk = f2u_mono(vs[e]) >> 24;
                    if (bk == lastb) cnt++;
                    else {
                        if (cnt) atomicAdd(&hsh[lastb], cnt);
                        lastb = bk; cnt = 1;
                    }
                }
            }
        }
        if (cnt) atomicAdd(&hsh[lastb], cnt);
        __syncthreads();
        if (hsh[tid]) atomicAdd(&g_hist4[tid], hsh[tid]);
    } else {
        float g1 = g_gamma[0], g2 = g_gamma[1];
        float csum[4][2];
        #pragma unroll
        for (int ni = 0; ni < 4; ni++) { csum[ni][0] = 0.f; csum[ni][1] = 0.f; }

        #pragma unroll
        for (int mi = 0; mi < 4; mi++) {
            int i_lo = i0 + warp_m * 64 + mi * 16 + qrow;
            int i_hi = i_lo + 8;
            float xlo = x2[i_lo], xhi = x2[i_hi];
            float slo = 0.f, shi = 0.f;
            #pragma unroll
            for (int ni = 0; ni < 4; ni++) {
                int j = j0 + warp_n * 32 + ni * 8 + qcol;
                float yj0 = y2[j], yj1 = y2[j + 1];
                float d0 = (xlo + yj0 - 2.f * acc[mi][ni][0]) * 0.00390625f;
                float d1 = (xlo + yj1 - 2.f * acc[mi][ni][1]) * 0.00390625f;
                float d2v = (xhi + yj0 - 2.f * acc[mi][ni][2]) * 0.00390625f;
                float d3 = (xhi + yj1 - 2.f * acc[mi][ni][3]) * 0.00390625f;
                float e0 = __expf(-g1 * d0)  + __expf(-g2 * d0);
                float e1 = __expf(-g1 * d1)  + __expf(-g2 * d1);
                float e2 = __expf(-g1 * d2v) + __expf(-g2 * d2v);
                float e3 = __expf(-g1 * d3)  + __expf(-g2 * d3);
                slo += e0 + e1;
                shi += e2 + e3;
                csum[ni][0] += e0 + e2;
                csum[ni][1] += e1 + e3;
            }
            slo += __shfl_xor_sync(0xFFFFFFFFu, slo, 1);
            slo += __shfl_xor_sync(0xFFFFFFFFu, slo, 2);
            shi += __shfl_xor_sync(0xFFFFFFFFu, shi, 1);
            shi += __shfl_xor_sync(0xFFFFFFFFu, shi, 2);
            if ((lane & 3) == 0) {
                int col = tj * 4 + warp_n;
                g_selfpart[(size_t)i_lo * 128 + col] = slo;
                g_selfpart[(size_t)i_hi * 128 + col] = shi;
            }
        }
        if (ti != tj) {
            #pragma unroll
            for (int ni = 0; ni < 4; ni++) {
                #pragma unroll
                for (int cc = 0; cc < 2; cc++) {
                    float v = csum[ni][cc];
                    v += __shfl_xor_sync(0xFFFFFFFFu, v, 4);
                    v += __shfl_xor_sync(0xFFFFFFFFu, v, 8);
                    v += __shfl_xor_sync(0xFFFFFFFFu, v, 16);
                    if (lane < 4) {
                        int j = j0 + warp_n * 32 + ni * 8 + lane * 2 + cc;
                        g_selfpart2[(size_t)j * 64 + ti * 2 + warp_m] = v;
                    }
                }
            }
        }
    }
}

// ---------------------------------------------------------------------------
// 3) gamma_2 Gram: 64x64 tiles, 4x4/thread via float4 LDS, symmetric tiles,
//    z = 32 K-slabs of 128. (c2 from Gram diagonal in d2_final.)
// ---------------------------------------------------------------------------
__global__ __launch_bounds__(256)
void d2_part_kernel() {
    int p = blockIdx.x;                    // 10 upper-tri 64-tile pairs
    int ti = 0, rem = p;
    while (rem >= 4 - ti) { rem -= 4 - ti; ti++; }
    int tj = ti + rem;
    const int i0 = ti * 64, j0 = tj * 64;
    const int k0 = blockIdx.y * (N / NSLAB);

    __shared__ float Ei[32][64];
    __shared__ float Ej[32][64];
    const int tid = threadIdx.x;
    const int tx = tid & 15, ty = tid >> 4;

    float acc[4][4] = {};

    for (int kc = k0; kc < k0 + (N / NSLAB); kc += 32) {
        #pragma unroll
        for (int q = 0; q < 2; q++) {
            int idx = tid + q * 256;
            int kk = idx >> 4, c4 = (idx & 15) * 4;
            *(float4*)&Ei[kk][c4] =
                *(const float4*)&g_esa[(size_t)(kc + kk) * DIM + i0 + c4];
            *(float4*)&Ej[kk][c4] =
                *(const float4*)&g_esa[(size_t)(kc + kk) * DIM + j0 + c4];
        }
        __syncthreads();
        #pragma unroll
        for (int kk = 0; kk < 32; kk++) {
            float4 a = *(float4*)&Ei[kk][ty * 4];
            float4 b = *(float4*)&Ej[kk][tx * 4];
            acc[0][0] += a.x * b.x; acc[0][1] += a.x * b.y;
            acc[0][2] += a.x * b.z; acc[0][3] += a.x * b.w;
            acc[1][0] += a.y * b.x; acc[1][1] += a.y * b.y;
            acc[1][2] += a.y * b.z; acc[1][3] += a.y * b.w;
            acc[2][0] += a.z * b.x; acc[2][1] += a.z * b.y;
            acc[2][2] += a.z * b.z; acc[2][3] += a.z * b.w;
            acc[3][0] += a.w * b.x; acc[3][1] += a.w * b.y;
            acc[3][2] += a.w * b.z; acc[3][3] += a.w * b.w;
        }
        __syncthreads();
    }

    float* P = g_D2p + (size_t)blockIdx.y * DIM * DIM;
    #pragma unroll
    for (int r = 0; r < 4; r++) {
        #pragma unroll
        for (int c = 0; c < 4; c++)
            P[(size_t)(i0 + ty * 4 + r) * DIM + j0 + tx * 4 + c] = acc[r][c];
    }
}

__global__ void d2_final_kernel() {
    int i = blockIdx.x, t = threadIdx.x;
    __shared__ float diag[256];
    float dsum = 0.f;
    #pragma unroll
    for (int z = 0; z < NSLAB; z++)
        dsum += g_D2p[(size_t)z * DIM * DIM + t * DIM + t];
    diag[t] = dsum;
    size_t idx = ((i >> 6) <= (t >> 6)) ? (size_t)i * DIM + t
                                        : (size_t)t * DIM + i;
    float s = 0.f;
    #pragma unroll
    for (int z = 0; z < NSLAB; z++)
        s += g_D2p[(size_t)z * DIM * DIM + idx];
    __syncthreads();
    g_D2[i * DIM + t] = (diag[i] + diag[t] - 2.f * s) * (1.f / 4096.f);
}

// ---------------------------------------------------------------------------
// 4a) D2 median + gamma_2: one single-block kernel (all 4 radix passes)
// ---------------------------------------------------------------------------
__global__ __launch_bounds__(1024)
void d2_median_kernel() {
    __shared__ unsigned hist[256];
    __shared__ unsigned s[256];
    __shared__ unsigned sh_prefix, sh_k;
    int t = threadIdx.x;
    if (t == 0) { sh_prefix = 0u; sh_k = (DIM * DIM - 1) / 2; }
    __syncthreads();
    #pragma unroll
    for (int pass = 0; pass < 4; pass++) {
        if (t < 256) hist[t] = 0u;
        __syncthreads();
        int shift = 24 - pass * 8;
        unsigned prefix = sh_prefix;
        for (int i = t; i < DIM * DIM; i += 1024) {
            unsigned u = f2u_mono(g_D2[i]);
            bool ok = (pass == 0) || ((u >> (shift + 8)) == prefix);
            if (ok) atomicAdd(&hist[(u >> shift) & 0xFFu], 1u);
        }
        __syncthreads();
        unsigned kcur = sh_k;
        if (t < 256) s[t] = hist[t];
        __syncthreads();
        for (int off = 1; off < 256; off <<= 1) {
            unsigned v = (t < 256 && t >= off) ? s[t - off] : 0u;
            __syncthreads();
            if (t < 256) s[t] += v;
            __syncthreads();
        }
        if (t < 256) {
            unsigned c = hist[t];
            unsigned incl = s[t], excl = incl - c;
            if (kcur >= excl && kcur < incl) {
                sh_k = kcur - excl;
                sh_prefix = (prefix << 8) | (unsigned)t;
            }
        }
        __syncthreads();
    }
    if (t == 0) {
        unsigned u = sh_prefix;
        unsigned bits = (u & 0x80000000u) ? (u ^ 0x80000000u) : ~u;
        g_median[1] = __uint_as_float(bits);
        g_gamma[1]  = 1.0f / (__uint_as_float(bits) + EPS);
    }
}

// ---------------------------------------------------------------------------
// 4b) D median: scan-free chained hist passes (proven R8/R9 scheme)
// ---------------------------------------------------------------------------
__device__ __forceinline__ void chain_prefix(int npass, unsigned& prefix_out,
                                             unsigned& k_out,
                                             unsigned* s, unsigned* sh2) {
    int t = threadIdx.x;
    if (t == 0) { sh2[0] = 0u; sh2[1] = K_TARGET; }
    __syncthreads();
    for (int q = 0; q < npass; q++) {
        unsigned c = g_hist4[q * 256 + t];
        unsigned kcur = sh2[1];
        unsigned pfx  = sh2[0];
        __syncthreads();
        s[t] = c;
        __syncthreads();
        for (int off = 1; off < 256; off <<= 1) {
            unsigned v = (t >= off) ? s[t - off] : 0u;
            __syncthreads();
            s[t] += v;
            __syncthreads();
        }
        unsigned incl = s[t], excl = incl - c;
        if (kcur >= excl && kcur < incl) {
            sh2[1] = kcur - excl;
            sh2[0] = (pfx << 8) | (unsigned)t;
        }
        __syncthreads();
    }
    prefix_out = sh2[0];
    k_out = sh2[1];
}

__global__ __launch_bounds__(256)
void select_hist_chain(const float* __restrict__ data, unsigned n4, int pass) {
    __shared__ unsigned s[256];
    __shared__ unsigned sh2[2];
    __shared__ unsigned hloc[256];
    unsigned prefix, kdummy;
    chain_prefix(pass, prefix, kdummy, s, sh2);

    hloc[threadIdx.x] = 0u;
    __syncthreads();
    int shift = 24 - pass * 8;
    unsigned stride = gridDim.x * blockDim.x;
    int lane = threadIdx.x & 31;
    const float4* d4 = (const float4*)data;
    for (unsigned base = blockIdx.x * blockDim.x; base < n4; base += stride) {
        unsigned i = base + threadIdx.x;
        float4 v = make_float4(0.f, 0.f, 0.f, 0.f);
        bool valid = (i < n4);
        if (valid) v = d4[i];
        float vals[4] = {v.x, v.y, v.z, v.w};
        #pragma unroll
        for (int e = 0; e < 4; e++) {
            unsigned bucket = 0xFFFFFFFFu;
            if (valid) {
                unsigned u = f2u_mono(vals[e]);
                if ((u >> (shift + 8)) == prefix) bucket = (u >> shift) & 0xFFu;
            }
            unsigned m = __match_any_sync(0xFFFFFFFFu, bucket);
            if (bucket != 0xFFFFFFFFu && lane == __ffs(m) - 1)
                atomicAdd(&hloc[bucket], (unsigned)__popc(m));
        }
    }
    __syncthreads();
    if (hloc[threadIdx.x])
        atomicAdd(&g_hist4[pass * 256 + threadIdx.x], hloc[threadIdx.x]);
}

__global__ __launch_bounds__(256)
void select_finalize_chain() {
    __shared__ unsigned s[256];
    __shared__ unsigned sh2[2];
    unsigned prefix, kdummy;
    chain_prefix(4, prefix, kdummy, s, sh2);
    if (threadIdx.x == 0) {
        unsigned bits = (prefix & 0x80000000u) ? (prefix ^ 0x80000000u) : ~prefix;
        g_median[0] = __uint_as_float(bits);
        g_gamma[0]  = 1.0f / (__uint_as_float(bits) + EPS);
    }
}

// ---------------------------------------------------------------------------
// 5) Row means of exp over stored D (agent-expert pass)
// ---------------------------------------------------------------------------
__global__ __launch_bounds__(256)
void rowsum_kernel(const float* __restrict__ D) {
    int i = blockIdx.x, t = threadIdx.x;
    float g1 = g_gamma[0], g2 = g_gamma[1];
    const float4* row = (const float4*)(D + (size_t)i * N);
    float s = 0.f;
    #pragma unroll 4
    for (int j = t; j < N / 4; j += 256) {
        float4 v = row[j];
        s += __expf(-g1 * v.x) + __expf(-g1 * v.y) + __expf(-g1 * v.z) + __expf(-g1 * v.w)
           + __expf(-g2 * v.x) + __expf(-g2 * v.y) + __expf(-g2 * v.z) + __expf(-g2 * v.w);
    }
    __shared__ float sh[256];
    sh[t] = s;
    __syncthreads();
    #pragma unroll
    for (int k = 128; k > 0; k >>= 1) {
        if (t < k) sh[t] += sh[t + k];
        __syncthreads();
    }
    if (t == 0) g_sim[i] = sh[0] * (1.0f / (float)N);
}

// ---------------------------------------------------------------------------
// 6) final: out[i] = g_sim[i] - mean of valid self partials
// ---------------------------------------------------------------------------
__global__ void self_final_kernel(float* __restrict__ out) {
    int i = blockIdx.x * blockDim.x + threadIdx.x;
    int t = i >> 7;
    const float* rp = g_selfpart  + (size_t)i * 128;
    const float* cp = g_selfpart2 + (size_t)i * 64;
    float s = 0.f;
    for (int b = 4 * t; b < 128; b++) s += rp[b];
    for (int b = 0; b < 2 * t; b++)  s += cp[b];
    out[i] = g_sim[i] - s * (1.0f / (float)N);
}

// ---------------------------------------------------------------------------
// Host orchestration (graph-capturable)
// ---------------------------------------------------------------------------
extern "C" void kernel_launch(void* const* d_in, const int* in_sizes, int n_in,
                              void* d_out, int out_size) {
    const float* state   = (const float*)d_in[0];
    const float* action  = (const float*)d_in[1];
    const float* estate  = (const float*)d_in[2];
    const float* eaction = (const float*)d_in[3];
    float* out = (float*)d_out;

    float *p_sa, *p_esa, *p_x2, *p_y2, *p_D;
    __nv_bfloat16 *p_P, *p_Q, *p_R;
    cudaGetSymbolAddress((void**)&p_sa,  g_sa);
    cudaGetSymbolAddress((void**)&p_esa, g_esa);
    cudaGetSymbolAddress((void**)&p_x2,  g_x2);
    cudaGetSymbolAddress((void**)&p_y2,  g_y2);
    cudaGetSymbolAddress((void**)&p_D,   g_D);
    cudaGetSymbolAddress((void**)&p_P,   g_P);
    cudaGetSymbolAddress((void**)&p_Q,   g_Q);
    cudaGetSymbolAddress((void**)&p_R,   g_R);

    cudaFuncSetAttribute(hmma_dist_gemm<0>,
                         cudaFuncAttributeMaxDynamicSharedMemorySize, GM_SMEM);
    cudaFuncSetAttribute(hmma_dist_gemm<1>,
                         cudaFuncAttributeMaxDynamicSharedMemorySize, GM_SMEM);

    // 1) concat + norms + bf16 splits (also zeroes g_hist4)
    prep_kernel<<<N, 256>>>(state,  action,  p_sa,  p_x2, p_P, 1, p_Q);
    prep_kernel<<<N, 256>>>(estate, eaction, p_esa, p_y2, p_R, 0, nullptr);

    // 2) D_agent_expert + fused MSB histogram -> g_hist4[0]
    dim3 ggrid(N / 128, N / 128);
    hmma_dist_gemm<0><<<ggrid, 256, GM_SMEM>>>(p_P, p_R, p_x2, p_y2, p_D);

    // 3) gamma_2 matrix + single-launch median
    d2_part_kernel<<<dim3(10, NSLAB), 256>>>();
    d2_final_kernel<<<DIM, DIM>>>();
    d2_median_kernel<<<1, 1024>>>();

    // 4) D median passes 1..3 (pass 0 fused) + finalize/gamma_1
    {
        unsigned n4 = ((unsigned)N * (unsigned)N) / 4u;
        for (int p = 1; p <= 3; p++)
            select_hist_chain<<<2048, 256>>>(p_D, n4, p);
        select_finalize_chain<<<1, 256>>>();
    }

    // 5) agent-expert similarity means from stored D
    rowsum_kernel<<<N, 256>>>(p_D);

    // 6) self-distance GEMM, triangular, fused row+col sums
    hmma_dist_gemm<1><<<NTRI, 256, GM_SMEM>>>(p_P, p_Q, p_x2, p_x2, nullptr);
    self_final_kernel<<<N / 256, 256>>>(out);
}

// round 13
// speedup vs baseline: 1.2585x; 1.0486x over previous
#include <cuda_runtime.h>
#include <cuda_bf16.h>
#include <cuda_fp16.h>
#include <cstdint>
#include <cmath>

// ---------------------------------------------------------------------------
// Shapes: n1 = n2 = 4096, s = 192, a = 64, d = 256. Split-GEMM K = 768.
// ---------------------------------------------------------------------------
#define N      4096
#define DIM    256
#define SDIM   192
#define ADIM   64
#define KSPLIT 768
#define EPS    1e-8f
#define NSLAB  32

// ---------------------------------------------------------------------------
// Scratch (device globals — allocations forbidden)
// ---------------------------------------------------------------------------
__device__ __align__(256) float g_sa [N * DIM];
__device__ __align__(256) float g_esa[N * DIM];
__device__ __align__(256) float g_x2 [N];
__device__ __align__(256) float g_y2 [N];
__device__ __align__(256) float g_D  [(size_t)N * N];        // 64 MB
__device__ __align__(256) float g_D2 [DIM * DIM];
__device__ __align__(256) float g_D2p[NSLAB * DIM * DIM];
__device__ __align__(256) float g_sim[N];
__device__ __align__(256) float g_selfpart [(size_t)N * 128]; // row-sum slots
__device__ __align__(256) float g_selfpart2[(size_t)N * 64];  // col-sum slots
__device__ __align__(256) __nv_bfloat16 g_P[(size_t)N * KSPLIT]; // sa  [hi|hi|lo]
__device__ __align__(256) __nv_bfloat16 g_R[(size_t)N * KSPLIT]; // esa [hi|lo|hi]
__device__ __align__(256) __half        g_H[(size_t)N * DIM];    // sa fp16 (self GEMM)
__device__ unsigned g_hist4[4 * 256];  // per-pass histograms (prep zeroes)
__device__ float    g_median[2];
__device__ float    g_gamma[2];

#define K_TARGET 8388607u   // (N*N - 1) / 2

// ---------------------------------------------------------------------------
// helpers
// ---------------------------------------------------------------------------
__device__ __forceinline__ uint32_t smem_u32(const void* p) {
    uint32_t a;
    asm("{ .reg .u64 t; cvta.to.shared.u64 t, %1; cvt.u32.u64 %0, t; }"
        : "=r"(a) : "l"(p));
    return a;
}
#define SW128B(o) ((o) ^ (((o) >> 3) & 0x70))

__device__ __forceinline__ void cp_async16(uint32_t sdst, const void* gsrc) {
    asm volatile("cp.async.cg.shared.global [%0], [%1], 16;"
                 :: "r"(sdst), "l"(gsrc) : "memory");
}
__device__ __forceinline__ void cp_commit() {
    asm volatile("cp.async.commit_group;" ::: "memory");
}
__device__ __forceinline__ void ldmx4(uint32_t& r0, uint32_t& r1,
                                      uint32_t& r2, uint32_t& r3, uint32_t addr) {
    asm volatile("ldmatrix.sync.aligned.m8n8.x4.shared.b16 {%0,%1,%2,%3}, [%4];"
                 : "=r"(r0), "=r"(r1), "=r"(r2), "=r"(r3) : "r"(addr));
}
__device__ __forceinline__ void mma_bf16(float& c0, float& c1, float& c2, float& c3,
                                         uint32_t a0, uint32_t a1, uint32_t a2, uint32_t a3,
                                         uint32_t b0, uint32_t b1) {
    asm volatile(
        "mma.sync.aligned.m16n8k16.row.col.f32.bf16.bf16.f32 "
        "{%0,%1,%2,%3}, {%4,%5,%6,%7}, {%8,%9}, {%0,%1,%2,%3};"
        : "+f"(c0), "+f"(c1), "+f"(c2), "+f"(c3)
        : "r"(a0), "r"(a1), "r"(a2), "r"(a3), "r"(b0), "r"(b1));
}
__device__ __forceinline__ void mma_fp16(float& c0, float& c1, float& c2, float& c3,
                                         uint32_t a0, uint32_t a1, uint32_t a2, uint32_t a3,
                                         uint32_t b0, uint32_t b1) {
    asm volatile(
        "mma.sync.aligned.m16n8k16.row.col.f32.f16.f16.f32 "
        "{%0,%1,%2,%3}, {%4,%5,%6,%7}, {%8,%9}, {%0,%1,%2,%3};"
        : "+f"(c0), "+f"(c1), "+f"(c2), "+f"(c3)
        : "r"(a0), "r"(a1), "r"(a2), "r"(a3), "r"(b0), "r"(b1));
}
__device__ __forceinline__ unsigned f2u_mono(float f) {
    unsigned b = __float_as_uint(f);
    return (b & 0x80000000u) ? ~b : (b | 0x80000000u);
}

// ---------------------------------------------------------------------------
// 1) concat + norm + bf16 split (+ optional fp16 copy), fused. Zeroes g_hist4.
// ---------------------------------------------------------------------------
__global__ void prep_kernel(const float* __restrict__ st,
                            const float* __restrict__ ac,
                            float* __restrict__ cat, float* __restrict__ nrm,
                            __nv_bfloat16* __restrict__ dst0, int phl0,
                            __half* __restrict__ dstH) {
    int row = blockIdx.x, t = threadIdx.x;
    if (blockIdx.x < 4) g_hist4[blockIdx.x * 256 + t] = 0u;
    float v = (t < SDIM) ? st[row * SDIM + t] : ac[row * ADIM + (t - SDIM)];
    cat[row * DIM + t] = v;
    __nv_bfloat16 hi = __float2bfloat16(v);
    __nv_bfloat16 lo = __float2bfloat16(v - __bfloat162float(hi));
    size_t base = (size_t)row * KSPLIT + t;
    dst0[base]       = hi;
    dst0[base + 256] = phl0 ? hi : lo;
    dst0[base + 512] = phl0 ? lo : hi;
    if (dstH) dstH[(size_t)row * DIM + t] = __float2half(v);

    __shared__ float sh[256];
    sh[t] = v * v;
    __syncthreads();
    #pragma unroll
    for (int s = 128; s > 0; s >>= 1) {
        if (t < s) sh[t] += sh[t + s];
        __syncthreads();
    }
    if (t == 0) nrm[row] = sh[0];
}

// ---------------------------------------------------------------------------
// 2a) GEMM1 (agent-expert): bf16 split, K=768, 128x128 tile, 8 warps (2x4)
//     of 64x32, 3-stage cp.async, SW128 smem, 2 CTAs/SM.
//     Stores D + fused MSB histogram -> g_hist4[0].
// ---------------------------------------------------------------------------
#define BK        64
#define TILE_B    (128 * BK * 2)
#define STG       (2 * TILE_B)
#define GM_SMEM   (3 * STG)               // 96 KB
#define NCHUNK    12
#define NTILE     32
#define NTRI      (NTILE * (NTILE + 1) / 2)

template <typename T, int LDK>
__device__ __forceinline__ void gemm_issue_stage(
    const T* __restrict__ A, const T* __restrict__ B,
    int i0, int j0, int c, uint32_t sA, uint32_t sB, int tid)
{
    const T* Ap = A + (size_t)i0 * LDK + c * BK;
    const T* Bp = B + (size_t)j0 * LDK + c * BK;
    #pragma unroll
    for (int q = 0; q < 4; q++) {
        int idx = tid + q * 256;
        int row = idx >> 3, seg = idx & 7;
        cp_async16(sA + SW128B(row * 128 + seg * 16),
                   Ap + (size_t)row * LDK + seg * 8);
    }
    #pragma unroll
    for (int q = 0; q < 4; q++) {
        int idx = tid + q * 256;
        int row = idx >> 3, seg = idx & 7;
        cp_async16(sB + SW128B(row * 128 + seg * 16),
                   Bp + (size_t)row * LDK + seg * 8);
    }
    cp_commit();
}

__global__ __launch_bounds__(256, 2)
void hmma_dist_gemm(const __nv_bfloat16* __restrict__ A,
                    const __nv_bfloat16* __restrict__ B,
                    const float* __restrict__ x2,
                    const float* __restrict__ y2,
                    float* __restrict__ D)
{
    extern __shared__ char smem[];
    const uint32_t sb = smem_u32(smem);
    const int tid = threadIdx.x;
    const int wid = tid >> 5, lane = tid & 31;
    const int warp_m = wid >> 2, warp_n = wid & 3;
    const int i0 = blockIdx.y * 128;
    const int j0 = blockIdx.x * 128;

    uint32_t sA[3] = { sb,           sb + STG,           sb + 2 * STG };
    uint32_t sB[3] = { sb + TILE_B,  sb + STG + TILE_B,  sb + 2 * STG + TILE_B };

    float acc[4][4][4];
    #pragma unroll
    for (int mi = 0; mi < 4; mi++)
        #pragma unroll
        for (int ni = 0; ni < 4; ni++)
            #pragma unroll
            for (int e = 0; e < 4; e++) acc[mi][ni][e] = 0.f;

    gemm_issue_stage<__nv_bfloat16, KSPLIT>(A, B, i0, j0, 0, sA[0], sB[0], tid);
    gemm_issue_stage<__nv_bfloat16, KSPLIT>(A, B, i0, j0, 1, sA[1], sB[1], tid);
    gemm_issue_stage<__nv_bfloat16, KSPLIT>(A, B, i0, j0, 2, sA[2], sB[2], tid);

    const int a_row = (lane & 15);
    const int a_col = (lane & 16) ? 8 : 0;
    const int b_row = (lane & 7) + ((lane & 16) >> 1);
    const int b_col = (lane & 8) ? 8 : 0;

    for (int c = 0; c < NCHUNK; c++) {
        if (c < 10)      asm volatile("cp.async.wait_group 2;" ::: "memory");
        else if (c < 11) asm volatile("cp.async.wait_group 1;" ::: "memory");
        else             asm volatile("cp.async.wait_group 0;" ::: "memory");
        __syncthreads();

        int buf = c % 3;
        uint32_t cA = sA[buf], cB = sB[buf];
        #pragma unroll
        for (int ks = 0; ks < BK / 16; ks++) {
            int k0 = ks * 16;
            uint32_t a[4][4], b[2][4];
            #pragma unroll
            for (int mi = 0; mi < 4; mi++) {
                int row = warp_m * 64 + mi * 16 + a_row;
                ldmx4(a[mi][0], a[mi][1], a[mi][2], a[mi][3],
                      cA + SW128B(row * 128 + (k0 + a_col) * 2));
            }
            #pragma unroll
            for (int nb = 0; nb < 2; nb++) {
                int row = warp_n * 32 + nb * 16 + b_row;
                ldmx4(b[nb][0], b[nb][1], b[nb][2], b[nb][3],
                      cB + SW128B(row * 128 + (k0 + b_col) * 2));
            }
            #pragma unroll
            for (int mi = 0; mi < 4; mi++)
                #pragma unroll
                for (int ni = 0; ni < 4; ni++)
                    mma_bf16(acc[mi][ni][0], acc[mi][ni][1],
                             acc[mi][ni][2], acc[mi][ni][3],
                             a[mi][0], a[mi][1], a[mi][2], a[mi][3],
                             b[ni >> 1][(ni & 1) * 2], b[ni >> 1][(ni & 1) * 2 + 1]);
        }
        __syncthreads();
        if (c + 3 < NCHUNK)
            gemm_issue_stage<__nv_bfloat16, KSPLIT>(A, B, i0, j0, c + 3,
                                                    sA[buf], sB[buf], tid);
    }

    const int qrow = lane >> 2;
    const int qcol = (lane & 3) * 2;

    unsigned* hsh = (unsigned*)smem;
    hsh[tid] = 0u;
    __syncthreads();
    unsigned lastb = 0xFFFFFFFFu, cnt = 0;

    #pragma unroll
    for (int mi = 0; mi < 4; mi++) {
        int i_lo = i0 + warp_m * 64 + mi * 16 + qrow;
        int i_hi = i_lo + 8;
        float xlo = x2[i_lo], xhi = x2[i_hi];
        #pragma unroll
        for (int ni = 0; ni < 4; ni++) {
            int j = j0 + warp_n * 32 + ni * 8 + qcol;
            float yj0 = y2[j], yj1 = y2[j + 1];
            float2 vlo, vhi;
            vlo.x = (xlo + yj0 - 2.f * acc[mi][ni][0]) * 0.00390625f;
            vlo.y = (xlo + yj1 - 2.f * acc[mi][ni][1]) * 0.00390625f;
            vhi.x = (xhi + yj0 - 2.f * acc[mi][ni][2]) * 0.00390625f;
            vhi.y = (xhi + yj1 - 2.f * acc[mi][ni][3]) * 0.00390625f;
            *(float2*)(D + (size_t)i_lo * N + j) = vlo;
            *(float2*)(D + (size_t)i_hi * N + j) = vhi;
            float vs[4] = {vlo.x, vlo.y, vhi.x, vhi.y};
            #pragma unroll
            for (int e = 0; e < 4; e++) {
                unsigned bk = f2u_mono(vs[e]) >> 24;
                if (bk == lastb) cnt++;
                else {
                    if (cnt) atomicAdd(&hsh[lastb], cnt);
                    lastb = bk; cnt = 1;
                }
            }
        }
    }
    if (cnt) atomicAdd(&hsh[lastb], cnt);
    __syncthreads();
    if (hsh[tid]) atomicAdd(&g_hist4[tid], hsh[tid]);
}

// ---------------------------------------------------------------------------
// 2b) GEMM2 (self): plain fp16, K=256 (4 chunks), triangular grid,
//     fused row+col exp-sums, no D materialization.
// ---------------------------------------------------------------------------
#define NCHUNK2 4

__global__ __launch_bounds__(256, 2)
void hmma_self_fp16(const __half* __restrict__ H,
                    const float* __restrict__ x2)
{
    extern __shared__ char smem[];
    const uint32_t sb = smem_u32(smem);
    const int tid = threadIdx.x;
    const int wid = tid >> 5, lane = tid & 31;
    const int warp_m = wid >> 2, warp_n = wid & 3;

    int bid = blockIdx.x;
    int ti = (int)(32.5f - sqrtf(32.5f * 32.5f - 2.0f * (float)bid));
    while (NTILE * ti - ti * (ti - 1) / 2 > bid) ti--;
    while (NTILE * (ti + 1) - (ti + 1) * ti / 2 <= bid) ti++;
    int tj = ti + (bid - (NTILE * ti - ti * (ti - 1) / 2));
    const int i0 = ti * 128;
    const int j0 = tj * 128;

    uint32_t sA[3] = { sb,           sb + STG,           sb + 2 * STG };
    uint32_t sB[3] = { sb + TILE_B,  sb + STG + TILE_B,  sb + 2 * STG + TILE_B };

    float acc[4][4][4];
    #pragma unroll
    for (int mi = 0; mi < 4; mi++)
        #pragma unroll
        for (int ni = 0; ni < 4; ni++)
            #pragma unroll
            for (int e = 0; e < 4; e++) acc[mi][ni][e] = 0.f;

    gemm_issue_stage<__half, DIM>(H, H, i0, j0, 0, sA[0], sB[0], tid);
    gemm_issue_stage<__half, DIM>(H, H, i0, j0, 1, sA[1], sB[1], tid);
    gemm_issue_stage<__half, DIM>(H, H, i0, j0, 2, sA[2], sB[2], tid);

    const int a_row = (lane & 15);
    const int a_col = (lane & 16) ? 8 : 0;
    const int b_row = (lane & 7) + ((lane & 16) >> 1);
    const int b_col = (lane & 8) ? 8 : 0;

    for (int c = 0; c < NCHUNK2; c++) {
        if (c < 2)       asm volatile("cp.async.wait_group 2;" ::: "memory");
        else if (c < 3)  asm volatile("cp.async.wait_group 1;" ::: "memory");
        else             asm volatile("cp.async.wait_group 0;" ::: "memory");
        __syncthreads();

        int buf = c % 3;
        uint32_t cA = sA[buf], cB = sB[buf];
        #pragma unroll
        for (int ks = 0; ks < BK / 16; ks++) {
            int k0 = ks * 16;
            uint32_t a[4][4], b[2][4];
            #pragma unroll
            for (int mi = 0; mi < 4; mi++) {
                int row = warp_m * 64 + mi * 16 + a_row;
                ldmx4(a[mi][0], a[mi][1], a[mi][2], a[mi][3],
                      cA + SW128B(row * 128 + (k0 + a_col) * 2));
            }
            #pragma unroll
            for (int nb = 0; nb < 2; nb++) {
                int row = warp_n * 32 + nb * 16 + b_row;
                ldmx4(b[nb][0], b[nb][1], b[nb][2], b[nb][3],
                      cB + SW128B(row * 128 + (k0 + b_col) * 2));
            }
            #pragma unroll
            for (int mi = 0; mi < 4; mi++)
                #pragma unroll
                for (int ni = 0; ni < 4; ni++)
                    mma_fp16(acc[mi][ni][0], acc[mi][ni][1],
                             acc[mi][ni][2], acc[mi][ni][3],
                             a[mi][0], a[mi][1], a[mi][2], a[mi][3],
                             b[ni >> 1][(ni & 1) * 2], b[ni >> 1][(ni & 1) * 2 + 1]);
        }
        __syncthreads();
        if (c + 3 < NCHUNK2)
            gemm_issue_stage<__half, DIM>(H, H, i0, j0, c + 3,
                                          sA[buf], sB[buf], tid);
    }

    const int qrow = lane >> 2;
    const int qcol = (lane & 3) * 2;

    float g1 = g_gamma[0], g2 = g_gamma[1];
    float csum[4][2];
    #pragma unroll
    for (int ni = 0; ni < 4; ni++) { csum[ni][0] = 0.f; csum[ni][1] = 0.f; }

    #pragma unroll
    for (int mi = 0; mi < 4; mi++) {
        int i_lo = i0 + warp_m * 64 + mi * 16 + qrow;
        int i_hi = i_lo + 8;
        float xlo = x2[i_lo], xhi = x2[i_hi];
        float slo = 0.f, shi = 0.f;
        #pragma unroll
        for (int ni = 0; ni < 4; ni++) {
            int j = j0 + warp_n * 32 + ni * 8 + qcol;
            float yj0 = x2[j], yj1 = x2[j + 1];
            float d0 = (xlo + yj0 - 2.f * acc[mi][ni][0]) * 0.00390625f;
            float d1 = (xlo + yj1 - 2.f * acc[mi][ni][1]) * 0.00390625f;
            float d2v = (xhi + yj0 - 2.f * acc[mi][ni][2]) * 0.00390625f;
            float d3 = (xhi + yj1 - 2.f * acc[mi][ni][3]) * 0.00390625f;
            float e0 = __expf(-g1 * d0)  + __expf(-g2 * d0);
            float e1 = __expf(-g1 * d1)  + __expf(-g2 * d1);
            float e2 = __expf(-g1 * d2v) + __expf(-g2 * d2v);
            float e3 = __expf(-g1 * d3)  + __expf(-g2 * d3);
            slo += e0 + e1;
            shi += e2 + e3;
            csum[ni][0] += e0 + e2;
            csum[ni][1] += e1 + e3;
        }
        slo += __shfl_xor_sync(0xFFFFFFFFu, slo, 1);
        slo += __shfl_xor_sync(0xFFFFFFFFu, slo, 2);
        shi += __shfl_xor_sync(0xFFFFFFFFu, shi, 1);
        shi += __shfl_xor_sync(0xFFFFFFFFu, shi, 2);
        if ((lane & 3) == 0) {
            int col = tj * 4 + warp_n;
            g_selfpart[(size_t)i_lo * 128 + col] = slo;
            g_selfpart[(size_t)i_hi * 128 + col] = shi;
        }
    }
    if (ti != tj) {
        #pragma unroll
        for (int ni = 0; ni < 4; ni++) {
            #pragma unroll
            for (int cc = 0; cc < 2; cc++) {
                float v = csum[ni][cc];
                v += __shfl_xor_sync(0xFFFFFFFFu, v, 4);
                v += __shfl_xor_sync(0xFFFFFFFFu, v, 8);
                v += __shfl_xor_sync(0xFFFFFFFFu, v, 16);
                if (lane < 4) {
                    int j = j0 + warp_n * 32 + ni * 8 + lane * 2 + cc;
                    g_selfpart2[(size_t)j * 64 + ti * 2 + warp_m] = v;
                }
            }
        }
    }
}

// ---------------------------------------------------------------------------
// 3) gamma_2 Gram: 64x64 tiles, float4 LDS, symmetric tiles, 32 K-slabs.
// ---------------------------------------------------------------------------
__global__ __launch_bounds__(256)
void d2_part_kernel() {
    int p = blockIdx.x;
    int ti = 0, rem = p;
    while (rem >= 4 - ti) { rem -= 4 - ti; ti++; }
    int tj = ti + rem;
    const int i0 = ti * 64, j0 = tj * 64;
    const int k0 = blockIdx.y * (N / NSLAB);

    __shared__ float Ei[32][64];
    __shared__ float Ej[32][64];
    const int tid = threadIdx.x;
    const int tx = tid & 15, ty = tid >> 4;

    float acc[4][4] = {};

    for (int kc = k0; kc < k0 + (N / NSLAB); kc += 32) {
        #pragma unroll
        for (int q = 0; q < 2; q++) {
            int idx = tid + q * 256;
            int kk = idx >> 4, c4 = (idx & 15) * 4;
            *(float4*)&Ei[kk][c4] =
                *(const float4*)&g_esa[(size_t)(kc + kk) * DIM + i0 + c4];
            *(float4*)&Ej[kk][c4] =
                *(const float4*)&g_esa[(size_t)(kc + kk) * DIM + j0 + c4];
        }
        __syncthreads();
        #pragma unroll
        for (int kk = 0; kk < 32; kk++) {
            float4 a = *(float4*)&Ei[kk][ty * 4];
            float4 b = *(float4*)&Ej[kk][tx * 4];
            acc[0][0] += a.x * b.x; acc[0][1] += a.x * b.y;
            acc[0][2] += a.x * b.z; acc[0][3] += a.x * b.w;
            acc[1][0] += a.y * b.x; acc[1][1] += a.y * b.y;
            acc[1][2] += a.y * b.z; acc[1][3] += a.y * b.w;
            acc[2][0] += a.z * b.x; acc[2][1] += a.z * b.y;
            acc[2][2] += a.z * b.z; acc[2][3] += a.z * b.w;
            acc[3][0] += a.w * b.x; acc[3][1] += a.w * b.y;
            acc[3][2] += a.w * b.z; acc[3][3] += a.w * b.w;
        }
        __syncthreads();
    }

    float* P = g_D2p + (size_t)blockIdx.y * DIM * DIM;
    #pragma unroll
    for (int r = 0; r < 4; r++) {
        #pragma unroll
        for (int c = 0; c < 4; c++)
            P[(size_t)(i0 + ty * 4 + r) * DIM + j0 + tx * 4 + c] = acc[r][c];
    }
}

__global__ void d2_final_kernel() {
    int i = blockIdx.x, t = threadIdx.x;
    __shared__ float diag[256];
    float dsum = 0.f;
    #pragma unroll
    for (int z = 0; z < NSLAB; z++)
        dsum += g_D2p[(size_t)z * DIM * DIM + t * DIM + t];
    diag[t] = dsum;
    size_t idx = ((i >> 6) <= (t >> 6)) ? (size_t)i * DIM + t
                                        : (size_t)t * DIM + i;
    float s = 0.f;
    #pragma unroll
    for (int z = 0; z < NSLAB; z++)
        s += g_D2p[(size_t)z * DIM * DIM + idx];
    __syncthreads();
    g_D2[i * DIM + t] = (diag[i] + diag[t] - 2.f * s) * (1.f / 4096.f);
}

// ---------------------------------------------------------------------------
// 4a) D2 median + gamma_2: one single-block kernel
// ---------------------------------------------------------------------------
__global__ __launch_bounds__(1024)
void d2_median_kernel() {
    __shared__ unsigned hist[256];
    __shared__ unsigned s[256];
    __shared__ unsigned sh_prefix, sh_k;
    int t = threadIdx.x;
    if (t == 0) { sh_prefix = 0u; sh_k = (DIM * DIM - 1) / 2; }
    __syncthreads();
    #pragma unroll
    for (int pass = 0; pass < 4; pass++) {
        if (t < 256) hist[t] = 0u;
        __syncthreads();
        int shift = 24 - pass * 8;
        unsigned prefix = sh_prefix;
        for (int i = t; i < DIM * DIM; i += 1024) {
            unsigned u = f2u_mono(g_D2[i]);
            bool ok = (pass == 0) || ((u >> (shift + 8)) == prefix);
            if (ok) atomicAdd(&hist[(u >> shift) & 0xFFu], 1u);
        }
        __syncthreads();
        unsigned kcur = sh_k;
        if (t < 256) s[t] = hist[t];
        __syncthreads();
        for (int off = 1; off < 256; off <<= 1) {
            unsigned v = (t < 256 && t >= off) ? s[t - off] : 0u;
            __syncthreads();
            if (t < 256) s[t] += v;
            __syncthreads();
        }
        if (t < 256) {
            unsigned c = hist[t];
            unsigned incl = s[t], excl = incl - c;
            if (kcur >= excl && kcur < incl) {
                sh_k = kcur - excl;
                sh_prefix = (prefix << 8) | (unsigned)t;
            }
        }
        __syncthreads();
    }
    if (t == 0) {
        unsigned u = sh_prefix;
        unsigned bits = (u & 0x80000000u) ? (u ^ 0x80000000u) : ~u;
        g_median[1] = __uint_as_float(bits);
        g_gamma[1]  = 1.0f / (__uint_as_float(bits) + EPS);
    }
}

// ---------------------------------------------------------------------------
// 4b) D median: scan-free chained hist passes
// ---------------------------------------------------------------------------
__device__ __forceinline__ void chain_prefix(int npass, unsigned& prefix_out,
                                             unsigned& k_out,
                                             unsigned* s, unsigned* sh2) {
    int t = threadIdx.x;
    if (t == 0) { sh2[0] = 0u; sh2[1] = K_TARGET; }
    __syncthreads();
    for (int q = 0; q < npass; q++) {
        unsigned c = g_hist4[q * 256 + t];
        unsigned kcur = sh2[1];
        unsigned pfx  = sh2[0];
        __syncthreads();
        s[t] = c;
        __syncthreads();
        for (int off = 1; off < 256; off <<= 1) {
            unsigned v = (t >= off) ? s[t - off] : 0u;
            __syncthreads();
            s[t] += v;
            __syncthreads();
        }
        unsigned incl = s[t], excl = incl - c;
        if (kcur >= excl && kcur < incl) {
            sh2[1] = kcur - excl;
            sh2[0] = (pfx << 8) | (unsigned)t;
        }
        __syncthreads();
    }
    prefix_out = sh2[0];
    k_out = sh2[1];
}

__global__ __launch_bounds__(256)
void select_hist_chain(const float* __restrict__ data, unsigned n4, int pass) {
    __shared__ unsigned s[256];
    __shared__ unsigned sh2[2];
    __shared__ unsigned hloc[256];
    unsigned prefix, kdummy;
    chain_prefix(pass, prefix, kdummy, s, sh2);

    hloc[threadIdx.x] = 0u;
    __syncthreads();
    int shift = 24 - pass * 8;
    unsigned stride = gridDim.x * blockDim.x;
    int lane = threadIdx.x & 31;
    const float4* d4 = (const float4*)data;
    for (unsigned base = blockIdx.x * blockDim.x; base < n4; base += stride) {
        unsigned i = base + threadIdx.x;
        float4 v = make_float4(0.f, 0.f, 0.f, 0.f);
        bool valid = (i < n4);
        if (valid) v = d4[i];
        float vals[4] = {v.x, v.y, v.z, v.w};
        #pragma unroll
        for (int e = 0; e < 4; e++) {
            unsigned bucket = 0xFFFFFFFFu;
            if (valid) {
                unsigned u = f2u_mono(vals[e]);
                if ((u >> (shift + 8)) == prefix) bucket = (u >> shift) & 0xFFu;
            }
            unsigned m = __match_any_sync(0xFFFFFFFFu, bucket);
            if (bucket != 0xFFFFFFFFu && lane == __ffs(m) - 1)
                atomicAdd(&hloc[bucket], (unsigned)__popc(m));
        }
    }
    __syncthreads();
    if (hloc[threadIdx.x])
        atomicAdd(&g_hist4[pass * 256 + threadIdx.x], hloc[threadIdx.x]);
}

__global__ __launch_bounds__(256)
void select_finalize_chain() {
    __shared__ unsigned s[256];
    __shared__ unsigned sh2[2];
    unsigned prefix, kdummy;
    chain_prefix(4, prefix, kdummy, s, sh2);
    if (threadIdx.x == 0) {
        unsigned bits = (prefix & 0x80000000u) ? (prefix ^ 0x80000000u) : ~prefix;
        g_median[0] = __uint_as_float(bits);
        g_gamma[0]  = 1.0f / (__uint_as_float(bits) + EPS);
    }
}

// ---------------------------------------------------------------------------
// 5) Row means of exp over stored D (agent-expert pass)
// ---------------------------------------------------------------------------
__global__ __launch_bounds__(256)
void rowsum_kernel(const float* __restrict__ D) {
    int i = blockIdx.x, t = threadIdx.x;
    float g1 = g_gamma[0], g2 = g_gamma[1];
    const float4* row = (const float4*)(D + (size_t)i * N);
    float s = 0.f;
    #pragma unroll 4
    for (int j = t; j < N / 4; j += 256) {
        float4 v = row[j];
        s += __expf(-g1 * v.x) + __expf(-g1 * v.y) + __expf(-g1 * v.z) + __expf(-g1 * v.w)
           + __expf(-g2 * v.x) + __expf(-g2 * v.y) + __expf(-g2 * v.z) + __expf(-g2 * v.w);
    }
    __shared__ float sh[256];
    sh[t] = s;
    __syncthreads();
    #pragma unroll
    for (int k = 128; k > 0; k >>= 1) {
        if (t < k) sh[t] += sh[t + k];
        __syncthreads();
    }
    if (t == 0) g_sim[i] = sh[0] * (1.0f / (float)N);
}

// ---------------------------------------------------------------------------
// 6) final: out[i] = g_sim[i] - mean of valid self partials
// ---------------------------------------------------------------------------
__global__ void self_final_kernel(float* __restrict__ out) {
    int i = blockIdx.x * blockDim.x + threadIdx.x;
    int t = i >> 7;
    const float* rp = g_selfpart  + (size_t)i * 128;
    const float* cp = g_selfpart2 + (size_t)i * 64;
    float s = 0.f;
    for (int b = 4 * t; b < 128; b++) s += rp[b];
    for (int b = 0; b < 2 * t; b++)  s += cp[b];
    out[i] = g_sim[i] - s * (1.0f / (float)N);
}

// ---------------------------------------------------------------------------
// Host orchestration (graph-capturable)
// ---------------------------------------------------------------------------
extern "C" void kernel_launch(void* const* d_in, const int* in_sizes, int n_in,
                              void* d_out, int out_size) {
    const float* state   = (const float*)d_in[0];
    const float* action  = (const float*)d_in[1];
    const float* estate  = (const float*)d_in[2];
    const float* eaction = (const float*)d_in[3];
    float* out = (float*)d_out;

    float *p_sa, *p_esa, *p_x2, *p_y2, *p_D;
    __nv_bfloat16 *p_P, *p_R;
    __half *p_H;
    cudaGetSymbolAddress((void**)&p_sa,  g_sa);
    cudaGetSymbolAddress((void**)&p_esa, g_esa);
    cudaGetSymbolAddress((void**)&p_x2,  g_x2);
    cudaGetSymbolAddress((void**)&p_y2,  g_y2);
    cudaGetSymbolAddress((void**)&p_D,   g_D);
    cudaGetSymbolAddress((void**)&p_P,   g_P);
    cudaGetSymbolAddress((void**)&p_R,   g_R);
    cudaGetSymbolAddress((void**)&p_H,   g_H);

    cudaFuncSetAttribute(hmma_dist_gemm,
                         cudaFuncAttributeMaxDynamicSharedMemorySize, GM_SMEM);
    cudaFuncSetAttribute(hmma_self_fp16,
                         cudaFuncAttributeMaxDynamicSharedMemorySize, GM_SMEM);

    // 1) concat + norms + splits (also zeroes g_hist4)
    prep_kernel<<<N, 256>>>(state,  action,  p_sa,  p_x2, p_P, 1, p_H);
    prep_kernel<<<N, 256>>>(estate, eaction, p_esa, p_y2, p_R, 0, nullptr);

    // 2) D_agent_expert (bf16 split) + fused MSB histogram -> g_hist4[0]
    dim3 ggrid(N / 128, N / 128);
    hmma_dist_gemm<<<ggrid, 256, GM_SMEM>>>(p_P, p_R, p_x2, p_y2, p_D);

    // 3) gamma_2 matrix + single-launch median
    d2_part_kernel<<<dim3(10, NSLAB), 256>>>();
    d2_final_kernel<<<DIM, DIM>>>();
    d2_median_kernel<<<1, 1024>>>();

    // 4) D median passes 1..3 (pass 0 fused) + finalize/gamma_1
    {
        unsigned n4 = ((unsigned)N * (unsigned)N) / 4u;
        for (int p = 1; p <= 3; p++)
            select_hist_chain<<<2048, 256>>>(p_D, n4, p);
        select_finalize_chain<<<1, 256>>>();
    }

    // 5) agent-expert similarity means from stored D
    rowsum_kernel<<<N, 256>>>(p_D);

    // 6) self-distance GEMM: fp16, K=256, triangular, fused row+col sums
    hmma_self_fp16<<<NTRI, 256, GM_SMEM>>>(p_H, p_x2);
    self_final_kernel<<<N / 256, 256>>>(out);
}

// round 14
// speedup vs baseline: 1.4908x; 1.1845x over previous
#include <cuda_runtime.h>
#include <cuda_fp16.h>
#include <cstdint>
#include <cmath>

// ---------------------------------------------------------------------------
// Shapes: n1 = n2 = 4096, s = 192, a = 64, d = 256. Both GEMMs fp16, K = 256.
// ---------------------------------------------------------------------------
#define N      4096
#define DIM    256
#define SDIM   192
#define ADIM   64
#define EPS    1e-8f
#define NSLAB  32

// ---------------------------------------------------------------------------
// Scratch (device globals — allocations forbidden)
// ---------------------------------------------------------------------------
__device__ __align__(256) float g_esa[N * DIM];               // expert fp32 (d2 path)
__device__ __align__(256) float g_x2 [N];
__device__ __align__(256) float g_y2 [N];
__device__ __align__(256) float g_D  [(size_t)N * N];         // 64 MB
__device__ __align__(256) float g_D2 [DIM * DIM];
__device__ __align__(256) float g_D2p[NSLAB * DIM * DIM];
__device__ __align__(256) float g_sim[N];
__device__ __align__(256) float g_selfpart [(size_t)N * 128]; // row-sum slots
__device__ __align__(256) float g_selfpart2[(size_t)N * 64];  // col-sum slots
__device__ __align__(256) __half g_HA[(size_t)N * DIM];       // sa  fp16
__device__ __align__(256) __half g_HB[(size_t)N * DIM];       // esa fp16
__device__ unsigned g_hist4[4 * 256];  // per-pass histograms (prep zeroes)
__device__ float    g_median[2];
__device__ float    g_gamma[2];

#define K_TARGET 8388607u   // (N*N - 1) / 2

// ---------------------------------------------------------------------------
// helpers
// ---------------------------------------------------------------------------
__device__ __forceinline__ uint32_t smem_u32(const void* p) {
    uint32_t a;
    asm("{ .reg .u64 t; cvta.to.shared.u64 t, %1; cvt.u32.u64 %0, t; }"
        : "=r"(a) : "l"(p));
    return a;
}
#define SW128B(o) ((o) ^ (((o) >> 3) & 0x70))

__device__ __forceinline__ void cp_async16(uint32_t sdst, const void* gsrc) {
    asm volatile("cp.async.cg.shared.global [%0], [%1], 16;"
                 :: "r"(sdst), "l"(gsrc) : "memory");
}
__device__ __forceinline__ void cp_commit() {
    asm volatile("cp.async.commit_group;" ::: "memory");
}
__device__ __forceinline__ void ldmx4(uint32_t& r0, uint32_t& r1,
                                      uint32_t& r2, uint32_t& r3, uint32_t addr) {
    asm volatile("ldmatrix.sync.aligned.m8n8.x4.shared.b16 {%0,%1,%2,%3}, [%4];"
                 : "=r"(r0), "=r"(r1), "=r"(r2), "=r"(r3) : "r"(addr));
}
__device__ __forceinline__ void mma_fp16(float& c0, float& c1, float& c2, float& c3,
                                         uint32_t a0, uint32_t a1, uint32_t a2, uint32_t a3,
                                         uint32_t b0, uint32_t b1) {
    asm volatile(
        "mma.sync.aligned.m16n8k16.row.col.f32.f16.f16.f32 "
        "{%0,%1,%2,%3}, {%4,%5,%6,%7}, {%8,%9}, {%0,%1,%2,%3};"
        : "+f"(c0), "+f"(c1), "+f"(c2), "+f"(c3)
        : "r"(a0), "r"(a1), "r"(a2), "r"(a3), "r"(b0), "r"(b1));
}
__device__ __forceinline__ unsigned f2u_mono(float f) {
    unsigned b = __float_as_uint(f);
    return (b & 0x80000000u) ? ~b : (b | 0x80000000u);
}

// ---------------------------------------------------------------------------
// 1) concat + norm + fp16 copy, fused. Zeroes g_hist4.
//    cat may be null (agent side needs no fp32 copy).
// ---------------------------------------------------------------------------
__global__ void prep_kernel(const float* __restrict__ st,
                            const float* __restrict__ ac,
                            float* __restrict__ cat, float* __restrict__ nrm,
                            __half* __restrict__ dstH) {
    int row = blockIdx.x, t = threadIdx.x;
    if (blockIdx.x < 4) g_hist4[blockIdx.x * 256 + t] = 0u;
    float v = (t < SDIM) ? st[row * SDIM + t] : ac[row * ADIM + (t - SDIM)];
    if (cat) cat[row * DIM + t] = v;
    dstH[(size_t)row * DIM + t] = __float2half(v);

    __shared__ float sh[256];
    sh[t] = v * v;
    __syncthreads();
    #pragma unroll
    for (int s = 128; s > 0; s >>= 1) {
        if (t < s) sh[t] += sh[t + s];
        __syncthreads();
    }
    if (t == 0) nrm[row] = sh[0];
}

// ---------------------------------------------------------------------------
// 2) HMMA distance GEMM — fp16, K=256 (4 chunks of BK=64), 128x128 CTA tile,
//    8 warps (2x4) of 64x32, 3-stage cp.async, SW128 smem, 2 CTAs/SM.
//    MODE 0: full grid; store D + fused MSB histogram -> g_hist4[0].
//    MODE 1: triangular grid (528 tiles); fused self row+col exp-sums, no D.
// ---------------------------------------------------------------------------
#define BK        64
#define TILE_B    (128 * BK * 2)
#define STG       (2 * TILE_B)
#define GM_SMEM   (3 * STG)               // 96 KB
#define NCHUNK    4
#define NTILE     32
#define NTRI      (NTILE * (NTILE + 1) / 2)

__device__ __forceinline__ void gemm_issue_stage(
    const __half* __restrict__ A, const __half* __restrict__ B,
    int i0, int j0, int c, uint32_t sA, uint32_t sB, int tid)
{
    const __half* Ap = A + (size_t)i0 * DIM + c * BK;
    const __half* Bp = B + (size_t)j0 * DIM + c * BK;
    #pragma unroll
    for (int q = 0; q < 4; q++) {
        int idx = tid + q * 256;
        int row = idx >> 3, seg = idx & 7;
        cp_async16(sA + SW128B(row * 128 + seg * 16),
                   Ap + (size_t)row * DIM + seg * 8);
    }
    #pragma unroll
    for (int q = 0; q < 4; q++) {
        int idx = tid + q * 256;
        int row = idx >> 3, seg = idx & 7;
        cp_async16(sB + SW128B(row * 128 + seg * 16),
                   Bp + (size_t)row * DIM + seg * 8);
    }
    cp_commit();
}

template <int MODE>
__global__ __launch_bounds__(256, 2)
void hmma_dist_gemm(const __half* __restrict__ A,
                    const __half* __restrict__ B,
                    const float* __restrict__ x2,
                    const float* __restrict__ y2,
                    float* __restrict__ D)
{
    extern __shared__ char smem[];
    const uint32_t sb = smem_u32(smem);
    const int tid = threadIdx.x;
    const int wid = tid >> 5, lane = tid & 31;
    const int warp_m = wid >> 2, warp_n = wid & 3;

    int ti, tj;
    if (MODE == 1) {
        int bid = blockIdx.x;
        ti = (int)(32.5f - sqrtf(32.5f * 32.5f - 2.0f * (float)bid));
        while (NTILE * ti - ti * (ti - 1) / 2 > bid) ti--;
        while (NTILE * (ti + 1) - (ti + 1) * ti / 2 <= bid) ti++;
        tj = ti + (bid - (NTILE * ti - ti * (ti - 1) / 2));
    } else {
        ti = blockIdx.y;
        tj = blockIdx.x;
    }
    const int i0 = ti * 128;
    const int j0 = tj * 128;

    uint32_t sA[3] = { sb,           sb + STG,           sb + 2 * STG };
    uint32_t sB[3] = { sb + TILE_B,  sb + STG + TILE_B,  sb + 2 * STG + TILE_B };

    float acc[4][4][4];
    #pragma unroll
    for (int mi = 0; mi < 4; mi++)
        #pragma unroll
        for (int ni = 0; ni < 4; ni++)
            #pragma unroll
            for (int e = 0; e < 4; e++) acc[mi][ni][e] = 0.f;

    gemm_issue_stage(A, B, i0, j0, 0, sA[0], sB[0], tid);
    gemm_issue_stage(A, B, i0, j0, 1, sA[1], sB[1], tid);
    gemm_issue_stage(A, B, i0, j0, 2, sA[2], sB[2], tid);

    const int a_row = (lane & 15);
    const int a_col = (lane & 16) ? 8 : 0;
    const int b_row = (lane & 7) + ((lane & 16) >> 1);
    const int b_col = (lane & 8) ? 8 : 0;

    for (int c = 0; c < NCHUNK; c++) {
        if (c < NCHUNK - 2)      asm volatile("cp.async.wait_group 2;" ::: "memory");
        else if (c < NCHUNK - 1) asm volatile("cp.async.wait_group 1;" ::: "memory");
        else                     asm volatile("cp.async.wait_group 0;" ::: "memory");
        __syncthreads();

        int buf = c % 3;
        uint32_t cA = sA[buf], cB = sB[buf];
        #pragma unroll
        for (int ks = 0; ks < BK / 16; ks++) {
            int k0 = ks * 16;
            uint32_t a[4][4], b[2][4];
            #pragma unroll
            for (int mi = 0; mi < 4; mi++) {
                int row = warp_m * 64 + mi * 16 + a_row;
                ldmx4(a[mi][0], a[mi][1], a[mi][2], a[mi][3],
                      cA + SW128B(row * 128 + (k0 + a_col) * 2));
            }
            #pragma unroll
            for (int nb = 0; nb < 2; nb++) {
                int row = warp_n * 32 + nb * 16 + b_row;
                ldmx4(b[nb][0], b[nb][1], b[nb][2], b[nb][3],
                      cB + SW128B(row * 128 + (k0 + b_col) * 2));
            }
            #pragma unroll
            for (int mi = 0; mi < 4; mi++)
                #pragma unroll
                for (int ni = 0; ni < 4; ni++)
                    mma_fp16(acc[mi][ni][0], acc[mi][ni][1],
                             acc[mi][ni][2], acc[mi][ni][3],
                             a[mi][0], a[mi][1], a[mi][2], a[mi][3],
                             b[ni >> 1][(ni & 1) * 2], b[ni >> 1][(ni & 1) * 2 + 1]);
        }
        __syncthreads();
        if (c + 3 < NCHUNK)
            gemm_issue_stage(A, B, i0, j0, c + 3, sA[buf], sB[buf], tid);
    }

    const int qrow = lane >> 2;
    const int qcol = (lane & 3) * 2;

    if (MODE == 0) {
        unsigned* hsh = (unsigned*)smem;
        hsh[tid] = 0u;
        __syncthreads();
        unsigned lastb = 0xFFFFFFFFu, cnt = 0;

        #pragma unroll
        for (int mi = 0; mi < 4; mi++) {
            int i_lo = i0 + warp_m * 64 + mi * 16 + qrow;
            int i_hi = i_lo + 8;
            float xlo = x2[i_lo], xhi = x2[i_hi];
            #pragma unroll
            for (int ni = 0; ni < 4; ni++) {
                int j = j0 + warp_n * 32 + ni * 8 + qcol;
                float yj0 = y2[j], yj1 = y2[j + 1];
                float2 vlo, vhi;
                vlo.x = (xlo + yj0 - 2.f * acc[mi][ni][0]) * 0.00390625f;
                vlo.y = (xlo + yj1 - 2.f * acc[mi][ni][1]) * 0.00390625f;
                vhi.x = (xhi + yj0 - 2.f * acc[mi][ni][2]) * 0.00390625f;
                vhi.y = (xhi + yj1 - 2.f * acc[mi][ni][3]) * 0.00390625f;
                *(float2*)(D + (size_t)i_lo * N + j) = vlo;
                *(float2*)(D + (size_t)i_hi * N + j) = vhi;
                float vs[4] = {vlo.x, vlo.y, vhi.x, vhi.y};
                #pragma unroll
                for (int e = 0; e < 4; e++) {
                    unsigned bk = f2u_mono(vs[e]) >> 24;
                    if (bk == lastb) cnt++;
                    else {
                        if (cnt) atomicAdd(&hsh[lastb], cnt);
                        lastb = bk; cnt = 1;
                    }
                }
            }
        }
        if (cnt) atomicAdd(&hsh[lastb], cnt);
        __syncthreads();
        if (hsh[tid]) atomicAdd(&g_hist4[tid], hsh[tid]);
    } else {
        float g1 = g_gamma[0], g2 = g_gamma[1];
        float csum[4][2];
        #pragma unroll
        for (int ni = 0; ni < 4; ni++) { csum[ni][0] = 0.f; csum[ni][1] = 0.f; }

        #pragma unroll
        for (int mi = 0; mi < 4; mi++) {
            int i_lo = i0 + warp_m * 64 + mi * 16 + qrow;
            int i_hi = i_lo + 8;
            float xlo = x2[i_lo], xhi = x2[i_hi];
            float slo = 0.f, shi = 0.f;
            #pragma unroll
            for (int ni = 0; ni < 4; ni++) {
                int j = j0 + warp_n * 32 + ni * 8 + qcol;
                float yj0 = x2[j], yj1 = x2[j + 1];
                float d0 = (xlo + yj0 - 2.f * acc[mi][ni][0]) * 0.00390625f;
                float d1 = (xlo + yj1 - 2.f * acc[mi][ni][1]) * 0.00390625f;
                float d2v = (xhi + yj0 - 2.f * acc[mi][ni][2]) * 0.00390625f;
                float d3 = (xhi + yj1 - 2.f * acc[mi][ni][3]) * 0.00390625f;
                float e0 = __expf(-g1 * d0)  + __expf(-g2 * d0);
                float e1 = __expf(-g1 * d1)  + __expf(-g2 * d1);
                float e2 = __expf(-g1 * d2v) + __expf(-g2 * d2v);
                float e3 = __expf(-g1 * d3)  + __expf(-g2 * d3);
                slo += e0 + e1;
                shi += e2 + e3;
                csum[ni][0] += e0 + e2;
                csum[ni][1] += e1 + e3;
            }
            slo += __shfl_xor_sync(0xFFFFFFFFu, slo, 1);
            slo += __shfl_xor_sync(0xFFFFFFFFu, slo, 2);
            shi += __shfl_xor_sync(0xFFFFFFFFu, shi, 1);
            shi += __shfl_xor_sync(0xFFFFFFFFu, shi, 2);
            if ((lane & 3) == 0) {
                int col = tj * 4 + warp_n;
                g_selfpart[(size_t)i_lo * 128 + col] = slo;
                g_selfpart[(size_t)i_hi * 128 + col] = shi;
            }
        }
        if (ti != tj) {
            #pragma unroll
            for (int ni = 0; ni < 4; ni++) {
                #pragma unroll
                for (int cc = 0; cc < 2; cc++) {
                    float v = csum[ni][cc];
                    v += __shfl_xor_sync(0xFFFFFFFFu, v, 4);
                    v += __shfl_xor_sync(0xFFFFFFFFu, v, 8);
                    v += __shfl_xor_sync(0xFFFFFFFFu, v, 16);
                    if (lane < 4) {
                        int j = j0 + warp_n * 32 + ni * 8 + lane * 2 + cc;
                        g_selfpart2[(size_t)j * 64 + ti * 2 + warp_m] = v;
                    }
                }
            }
        }
    }
}

// ---------------------------------------------------------------------------
// 3) gamma_2 Gram: 64x64 tiles, float4 LDS, symmetric tiles, 32 K-slabs.
// ---------------------------------------------------------------------------
__global__ __launch_bounds__(256)
void d2_part_kernel() {
    int p = blockIdx.x;
    int ti = 0, rem = p;
    while (rem >= 4 - ti) { rem -= 4 - ti; ti++; }
    int tj = ti + rem;
    const int i0 = ti * 64, j0 = tj * 64;
    const int k0 = blockIdx.y * (N / NSLAB);

    __shared__ float Ei[32][64];
    __shared__ float Ej[32][64];
    const int tid = threadIdx.x;
    const int tx = tid & 15, ty = tid >> 4;

    float acc[4][4] = {};

    for (int kc = k0; kc < k0 + (N / NSLAB); kc += 32) {
        #pragma unroll
        for (int q = 0; q < 2; q++) {
            int idx = tid + q * 256;
            int kk = idx >> 4, c4 = (idx & 15) * 4;
            *(float4*)&Ei[kk][c4] =
                *(const float4*)&g_esa[(size_t)(kc + kk) * DIM + i0 + c4];
            *(float4*)&Ej[kk][c4] =
                *(const float4*)&g_esa[(size_t)(kc + kk) * DIM + j0 + c4];
        }
        __syncthreads();
        #pragma unroll
        for (int kk = 0; kk < 32; kk++) {
            float4 a = *(float4*)&Ei[kk][ty * 4];
            float4 b = *(float4*)&Ej[kk][tx * 4];
            acc[0][0] += a.x * b.x; acc[0][1] += a.x * b.y;
            acc[0][2] += a.x * b.z; acc[0][3] += a.x * b.w;
            acc[1][0] += a.y * b.x; acc[1][1] += a.y * b.y;
            acc[1][2] += a.y * b.z; acc[1][3] += a.y * b.w;
            acc[2][0] += a.z * b.x; acc[2][1] += a.z * b.y;
            acc[2][2] += a.z * b.z; acc[2][3] += a.z * b.w;
            acc[3][0] += a.w * b.x; acc[3][1] += a.w * b.y;
            acc[3][2] += a.w * b.z; acc[3][3] += a.w * b.w;
        }
        __syncthreads();
    }

    float* P = g_D2p + (size_t)blockIdx.y * DIM * DIM;
    #pragma unroll
    for (int r = 0; r < 4; r++) {
        #pragma unroll
        for (int c = 0; c < 4; c++)
            P[(size_t)(i0 + ty * 4 + r) * DIM + j0 + tx * 4 + c] = acc[r][c];
    }
}

__global__ void d2_final_kernel() {
    int i = blockIdx.x, t = threadIdx.x;
    __shared__ float diag[256];
    float dsum = 0.f;
    #pragma unroll
    for (int z = 0; z < NSLAB; z++)
        dsum += g_D2p[(size_t)z * DIM * DIM + t * DIM + t];
    diag[t] = dsum;
    size_t idx = ((i >> 6) <= (t >> 6)) ? (size_t)i * DIM + t
                                        : (size_t)t * DIM + i;
    float s = 0.f;
    #pragma unroll
    for (int z = 0; z < NSLAB; z++)
        s += g_D2p[(size_t)z * DIM * DIM + idx];
    __syncthreads();
    g_D2[i * DIM + t] = (diag[i] + diag[t] - 2.f * s) * (1.f / 4096.f);
}

// ---------------------------------------------------------------------------
// 4a) D2 median + gamma_2: one single-block kernel
// ---------------------------------------------------------------------------
__global__ __launch_bounds__(1024)
void d2_median_kernel() {
    __shared__ unsigned hist[256];
    __shared__ unsigned s[256];
    __shared__ unsigned sh_prefix, sh_k;
    int t = threadIdx.x;
    if (t == 0) { sh_prefix = 0u; sh_k = (DIM * DIM - 1) / 2; }
    __syncthreads();
    #pragma unroll
    for (int pass = 0; pass < 4; pass++) {
        if (t < 256) hist[t] = 0u;
        __syncthreads();
        int shift = 24 - pass * 8;
        unsigned prefix = sh_prefix;
        for (int i = t; i < DIM * DIM; i += 1024) {
            unsigned u = f2u_mono(g_D2[i]);
            bool ok = (pass == 0) || ((u >> (shift + 8)) == prefix);
            if (ok) atomicAdd(&hist[(u >> shift) & 0xFFu], 1u);
        }
        __syncthreads();
        unsigned kcur = sh_k;
        if (t < 256) s[t] = hist[t];
        __syncthreads();
        for (int off = 1; off < 256; off <<= 1) {
            unsigned v = (t < 256 && t >= off) ? s[t - off] : 0u;
            __syncthreads();
            if (t < 256) s[t] += v;
            __syncthreads();
        }
        if (t < 256) {
            unsigned c = hist[t];
            unsigned incl = s[t], excl = incl - c;
            if (kcur >= excl && kcur < incl) {
                sh_k = kcur - excl;
                sh_prefix = (prefix << 8) | (unsigned)t;
            }
        }
        __syncthreads();
    }
    if (t == 0) {
        unsigned u = sh_prefix;
        unsigned bits = (u & 0x80000000u) ? (u ^ 0x80000000u) : ~u;
        g_median[1] = __uint_as_float(bits);
        g_gamma[1]  = 1.0f / (__uint_as_float(bits) + EPS);
    }
}

// ---------------------------------------------------------------------------
// 4b) D median: scan-free chained hist passes
// ---------------------------------------------------------------------------
__device__ __forceinline__ void chain_prefix(int npass, unsigned& prefix_out,
                                             unsigned& k_out,
                                             unsigned* s, unsigned* sh2) {
    int t = threadIdx.x;
    if (t == 0) { sh2[0] = 0u; sh2[1] = K_TARGET; }
    __syncthreads();
    for (int q = 0; q < npass; q++) {
        unsigned c = g_hist4[q * 256 + t];
        unsigned kcur = sh2[1];
        unsigned pfx  = sh2[0];
        __syncthreads();
        s[t] = c;
        __syncthreads();
        for (int off = 1; off < 256; off <<= 1) {
            unsigned v = (t >= off) ? s[t - off] : 0u;
            __syncthreads();
            s[t] += v;
            __syncthreads();
        }
        unsigned incl = s[t], excl = incl - c;
        if (kcur >= excl && kcur < incl) {
            sh2[1] = kcur - excl;
            sh2[0] = (pfx << 8) | (unsigned)t;
        }
        __syncthreads();
    }
    prefix_out = sh2[0];
    k_out = sh2[1];
}

__global__ __launch_bounds__(256)
void select_hist_chain(const float* __restrict__ data, unsigned n4, int pass) {
    __shared__ unsigned s[256];
    __shared__ unsigned sh2[2];
    __shared__ unsigned hloc[256];
    unsigned prefix, kdummy;
    chain_prefix(pass, prefix, kdummy, s, sh2);

    hloc[threadIdx.x] = 0u;
    __syncthreads();
    int shift = 24 - pass * 8;
    unsigned stride = gridDim.x * blockDim.x;
    int lane = threadIdx.x & 31;
    const float4* d4 = (const float4*)data;
    for (unsigned base = blockIdx.x * blockDim.x; base < n4; base += stride) {
        unsigned i = base + threadIdx.x;
        float4 v = make_float4(0.f, 0.f, 0.f, 0.f);
        bool valid = (i < n4);
        if (valid) v = d4[i];
        float vals[4] = {v.x, v.y, v.z, v.w};
        #pragma unroll
        for (int e = 0; e < 4; e++) {
            unsigned bucket = 0xFFFFFFFFu;
            if (valid) {
                unsigned u = f2u_mono(vals[e]);
                if ((u >> (shift + 8)) == prefix) bucket = (u >> shift) & 0xFFu;
            }
            unsigned m = __match_any_sync(0xFFFFFFFFu, bucket);
            if (bucket != 0xFFFFFFFFu && lane == __ffs(m) - 1)
                atomicAdd(&hloc[bucket], (unsigned)__popc(m));
        }
    }
    __syncthreads();
    if (hloc[threadIdx.x])
        atomicAdd(&g_hist4[pass * 256 + threadIdx.x], hloc[threadIdx.x]);
}

__global__ __launch_bounds__(256)
void select_finalize_chain() {
    __shared__ unsigned s[256];
    __shared__ unsigned sh2[2];
    unsigned prefix, kdummy;
    chain_prefix(4, prefix, kdummy, s, sh2);
    if (threadIdx.x == 0) {
        unsigned bits = (prefix & 0x80000000u) ? (prefix ^ 0x80000000u) : ~prefix;
        g_median[0] = __uint_as_float(bits);
        g_gamma[0]  = 1.0f / (__uint_as_float(bits) + EPS);
    }
}

// ---------------------------------------------------------------------------
// 5) Row means of exp over stored D (agent-expert pass)
// ---------------------------------------------------------------------------
__global__ __launch_bounds__(256)
void rowsum_kernel(const float* __restrict__ D) {
    int i = blockIdx.x, t = threadIdx.x;
    float g1 = g_gamma[0], g2 = g_gamma[1];
    const float4* row = (const float4*)(D + (size_t)i * N);
    float s = 0.f;
    #pragma unroll 4
    for (int j = t; j < N / 4; j += 256) {
        float4 v = row[j];
        s += __expf(-g1 * v.x) + __expf(-g1 * v.y) + __expf(-g1 * v.z) + __expf(-g1 * v.w)
           + __expf(-g2 * v.x) + __expf(-g2 * v.y) + __expf(-g2 * v.z) + __expf(-g2 * v.w);
    }
    __shared__ float sh[256];
    sh[t] = s;
    __syncthreads();
    #pragma unroll
    for (int k = 128; k > 0; k >>= 1) {
        if (t < k) sh[t] += sh[t + k];
        __syncthreads();
    }
    if (t == 0) g_sim[i] = sh[0] * (1.0f / (float)N);
}

// ---------------------------------------------------------------------------
// 6) final: out[i] = g_sim[i] - mean of valid self partials
// ---------------------------------------------------------------------------
__global__ void self_final_kernel(float* __restrict__ out) {
    int i = blockIdx.x * blockDim.x + threadIdx.x;
    int t = i >> 7;
    const float* rp = g_selfpart  + (size_t)i * 128;
    const float* cp = g_selfpart2 + (size_t)i * 64;
    float s = 0.f;
    for (int b = 4 * t; b < 128; b++) s += rp[b];
    for (int b = 0; b < 2 * t; b++)  s += cp[b];
    out[i] = g_sim[i] - s * (1.0f / (float)N);
}

// ---------------------------------------------------------------------------
// Host orchestration (graph-capturable)
// ---------------------------------------------------------------------------
extern "C" void kernel_launch(void* const* d_in, const int* in_sizes, int n_in,
                              void* d_out, int out_size) {
    const float* state   = (const float*)d_in[0];
    const float* action  = (const float*)d_in[1];
    const float* estate  = (const float*)d_in[2];
    const float* eaction = (const float*)d_in[3];
    float* out = (float*)d_out;

    float *p_esa, *p_x2, *p_y2, *p_D;
    __half *p_HA, *p_HB;
    cudaGetSymbolAddress((void**)&p_esa, g_esa);
    cudaGetSymbolAddress((void**)&p_x2,  g_x2);
    cudaGetSymbolAddress((void**)&p_y2,  g_y2);
    cudaGetSymbolAddress((void**)&p_D,   g_D);
    cudaGetSymbolAddress((void**)&p_HA,  g_HA);
    cudaGetSymbolAddress((void**)&p_HB,  g_HB);

    cudaFuncSetAttribute(hmma_dist_gemm<0>,
                         cudaFuncAttributeMaxDynamicSharedMemorySize, GM_SMEM);
    cudaFuncSetAttribute(hmma_dist_gemm<1>,
                         cudaFuncAttributeMaxDynamicSharedMemorySize, GM_SMEM);

    // 1) concat + norms + fp16 copies (also zeroes g_hist4)
    prep_kernel<<<N, 256>>>(state,  action,  nullptr, p_x2, p_HA);
    prep_kernel<<<N, 256>>>(estate, eaction, p_esa,   p_y2, p_HB);

    // 2) D_agent_expert (fp16, K=256) + fused MSB histogram -> g_hist4[0]
    dim3 ggrid(N / 128, N / 128);
    hmma_dist_gemm<0><<<ggrid, 256, GM_SMEM>>>(p_HA, p_HB, p_x2, p_y2, p_D);

    // 3) gamma_2 matrix + single-launch median
    d2_part_kernel<<<dim3(10, NSLAB), 256>>>();
    d2_final_kernel<<<DIM, DIM>>>();
    d2_median_kernel<<<1, 1024>>>();

    // 4) D median passes 1..3 (pass 0 fused) + finalize/gamma_1
    {
        unsigned n4 = ((unsigned)N * (unsigned)N) / 4u;
        for (int p = 1; p <= 3; p++)
            select_hist_chain<<<2048, 256>>>(p_D, n4, p);
        select_finalize_chain<<<1, 256>>>();
    }

    // 5) agent-expert similarity means from stored D
    rowsum_kernel<<<N, 256>>>(p_D);

    // 6) self-distance GEMM: fp16, triangular, fused row+col sums
    hmma_dist_gemm<1><<<NTRI, 256, GM_SMEM>>>(p_HA, p_HA, p_x2, p_x2, nullptr);
    self_final_kernel<<<N / 256, 256>>>(out);
}

// round 16
// speedup vs baseline: 2.4131x; 1.6187x over previous
#include <cuda_runtime.h>
#include <cuda_fp16.h>
#include <cstdint>
#include <cmath>

// ---------------------------------------------------------------------------
// Shapes: n1 = n2 = 4096, s = 192, a = 64, d = 256. fp16 GEMMs.
// D stored as fp16 of (d - 2.0): distances concentrate at d~2, so shifting
// centers the fp16 binade on the data (ulp 2^-12 vs 2^-9 unshifted).
// ---------------------------------------------------------------------------
#define N      4096
#define DIM    256
#define SDIM   192
#define ADIM   64
#define EPS    1e-8f
#define NSLAB  32
#define DSHIFT 2.0f

// ---------------------------------------------------------------------------
// Scratch (device globals — allocations forbidden)
// ---------------------------------------------------------------------------
__device__ __align__(256) float  g_esa[N * DIM];               // expert fp32 (d2 path)
__device__ __align__(256) float  g_x2 [N];
__device__ __align__(256) float  g_y2 [N];
__device__ __align__(256) __half g_D  [(size_t)N * N];         // 32 MB fp16 (d-2)
__device__ __align__(256) float  g_D2 [DIM * DIM];
__device__ __align__(256) float  g_D2p[NSLAB * DIM * DIM];
__device__ __align__(256) float  g_sim[N];
__device__ __align__(256) float  g_selfpart [(size_t)N * 128]; // row-sum slots
__device__ __align__(256) float  g_selfpart2[(size_t)N * 64];  // col-sum slots
__device__ __align__(256) __half g_HA[(size_t)N * DIM];        // sa  fp16
__device__ __align__(256) __half g_HB[(size_t)N * DIM];        // esa fp16
__device__ unsigned g_hist2[2 * 256];  // pass-0 (fused) + pass-1 histograms
__device__ float    g_median[2];
__device__ float    g_gamma[2];

#define K_TARGET 8388607u   // (N*N - 1) / 2

// ---------------------------------------------------------------------------
// helpers
// ---------------------------------------------------------------------------
__device__ __forceinline__ uint32_t smem_u32(const void* p) {
    uint32_t a;
    asm("{ .reg .u64 t; cvta.to.shared.u64 t, %1; cvt.u32.u64 %0, t; }"
        : "=r"(a) : "l"(p));
    return a;
}
#define SW128B(o) ((o) ^ (((o) >> 3) & 0x70))

__device__ __forceinline__ void cp_async16(uint32_t sdst, const void* gsrc) {
    asm volatile("cp.async.cg.shared.global [%0], [%1], 16;"
                 :: "r"(sdst), "l"(gsrc) : "memory");
}
__device__ __forceinline__ void cp_commit() {
    asm volatile("cp.async.commit_group;" ::: "memory");
}
__device__ __forceinline__ void ldmx4(uint32_t& r0, uint32_t& r1,
                                      uint32_t& r2, uint32_t& r3, uint32_t addr) {
    asm volatile("ldmatrix.sync.aligned.m8n8.x4.shared.b16 {%0,%1,%2,%3}, [%4];"
                 : "=r"(r0), "=r"(r1), "=r"(r2), "=r"(r3) : "r"(addr));
}
__device__ __forceinline__ void mma_fp16(float& c0, float& c1, float& c2, float& c3,
                                         uint32_t a0, uint32_t a1, uint32_t a2, uint32_t a3,
                                         uint32_t b0, uint32_t b1) {
    asm volatile(
        "mma.sync.aligned.m16n8k16.row.col.f32.f16.f16.f32 "
        "{%0,%1,%2,%3}, {%4,%5,%6,%7}, {%8,%9}, {%0,%1,%2,%3};"
        : "+f"(c0), "+f"(c1), "+f"(c2), "+f"(c3)
        : "r"(a0), "r"(a1), "r"(a2), "r"(a3), "r"(b0), "r"(b1));
}
// 16-bit monotone key for fp16
__device__ __forceinline__ unsigned h2mono(unsigned short b) {
    return (b & 0x8000u) ? (unsigned)(unsigned short)~b
                         : (unsigned)(b | 0x8000u);
}
__device__ __forceinline__ unsigned f2u_mono(float f) {
    unsigned b = __float_as_uint(f);
    return (b & 0x80000000u) ? ~b : (b | 0x80000000u);
}

// ---------------------------------------------------------------------------
// 1) concat + norm + fp16 copy, fused. Zeroes g_hist2.
// ---------------------------------------------------------------------------
__global__ void prep_kernel(const float* __restrict__ st,
                            const float* __restrict__ ac,
                            float* __restrict__ cat, float* __restrict__ nrm,
                            __half* __restrict__ dstH) {
    int row = blockIdx.x, t = threadIdx.x;
    if (blockIdx.x < 2) g_hist2[blockIdx.x * 256 + t] = 0u;
    float v = (t < SDIM) ? st[row * SDIM + t] : ac[row * ADIM + (t - SDIM)];
    if (cat) cat[row * DIM + t] = v;
    dstH[(size_t)row * DIM + t] = __float2half(v);

    __shared__ float sh[256];
    sh[t] = v * v;
    __syncthreads();
    #pragma unroll
    for (int s = 128; s > 0; s >>= 1) {
        if (t < s) sh[t] += sh[t + s];
        __syncthreads();
    }
    if (t == 0) nrm[row] = sh[0];
}

// ---------------------------------------------------------------------------
// 2) HMMA distance GEMM — fp16, K=256 (4 chunks of BK=64), 128x128 CTA tile,
//    8 warps (2x4) of 64x32, 3-stage cp.async, SW128 smem, 2 CTAs/SM.
//    MODE 0: full grid; store fp16 (d-2) + fused top-byte histogram.
//    MODE 1: triangular grid (528 tiles); fused self row+col exp-sums, no D.
// ---------------------------------------------------------------------------
#define BK        64
#define TILE_B    (128 * BK * 2)
#define STG       (2 * TILE_B)
#define GM_SMEM   (3 * STG)               // 96 KB
#define NCHUNK    4
#define NTILE     32
#define NTRI      (NTILE * (NTILE + 1) / 2)

__device__ __forceinline__ void gemm_issue_stage(
    const __half* __restrict__ A, const __half* __restrict__ B,
    int i0, int j0, int c, uint32_t sA, uint32_t sB, int tid)
{
    const __half* Ap = A + (size_t)i0 * DIM + c * BK;
    const __half* Bp = B + (size_t)j0 * DIM + c * BK;
    #pragma unroll
    for (int q = 0; q < 4; q++) {
        int idx = tid + q * 256;
        int row = idx >> 3, seg = idx & 7;
        cp_async16(sA + SW128B(row * 128 + seg * 16),
                   Ap + (size_t)row * DIM + seg * 8);
    }
    #pragma unroll
    for (int q = 0; q < 4; q++) {
        int idx = tid + q * 256;
        int row = idx >> 3, seg = idx & 7;
        cp_async16(sB + SW128B(row * 128 + seg * 16),
                   Bp + (size_t)row * DIM + seg * 8);
    }
    cp_commit();
}

template <int MODE>
__global__ __launch_bounds__(256, 2)
void hmma_dist_gemm(const __half* __restrict__ A,
                    const __half* __restrict__ B,
                    const float* __restrict__ x2,
                    const float* __restrict__ y2,
                    __half* __restrict__ D)
{
    extern __shared__ char smem[];
    const uint32_t sb = smem_u32(smem);
    const int tid = threadIdx.x;
    const int wid = tid >> 5, lane = tid & 31;
    const int warp_m = wid >> 2, warp_n = wid & 3;

    int ti, tj;
    if (MODE == 1) {
        int bid = blockIdx.x;
        ti = (int)(32.5f - sqrtf(32.5f * 32.5f - 2.0f * (float)bid));
        while (NTILE * ti - ti * (ti - 1) / 2 > bid) ti--;
        while (NTILE * (ti + 1) - (ti + 1) * ti / 2 <= bid) ti++;
        tj = ti + (bid - (NTILE * ti - ti * (ti - 1) / 2));
    } else {
        ti = blockIdx.y;
        tj = blockIdx.x;
    }
    const int i0 = ti * 128;
    const int j0 = tj * 128;

    uint32_t sA[3] = { sb,           sb + STG,           sb + 2 * STG };
    uint32_t sB[3] = { sb + TILE_B,  sb + STG + TILE_B,  sb + 2 * STG + TILE_B };

    float acc[4][4][4];
    #pragma unroll
    for (int mi = 0; mi < 4; mi++)
        #pragma unroll
        for (int ni = 0; ni < 4; ni++)
            #pragma unroll
            for (int e = 0; e < 4; e++) acc[mi][ni][e] = 0.f;

    gemm_issue_stage(A, B, i0, j0, 0, sA[0], sB[0], tid);
    gemm_issue_stage(A, B, i0, j0, 1, sA[1], sB[1], tid);
    gemm_issue_stage(A, B, i0, j0, 2, sA[2], sB[2], tid);

    const int a_row = (lane & 15);
    const int a_col = (lane & 16) ? 8 : 0;
    const int b_row = (lane & 7) + ((lane & 16) >> 1);
    const int b_col = (lane & 8) ? 8 : 0;

    for (int c = 0; c < NCHUNK; c++) {
        if (c < NCHUNK - 2)      asm volatile("cp.async.wait_group 2;" ::: "memory");
        else if (c < NCHUNK - 1) asm volatile("cp.async.wait_group 1;" ::: "memory");
        else                     asm volatile("cp.async.wait_group 0;" ::: "memory");
        __syncthreads();

        int buf = c % 3;
        uint32_t cA = sA[buf], cB = sB[buf];
        #pragma unroll
        for (int ks = 0; ks < BK / 16; ks++) {
            int k0 = ks * 16;
            uint32_t a[4][4], b[2][4];
            #pragma unroll
            for (int mi = 0; mi < 4; mi++) {
                int row = warp_m * 64 + mi * 16 + a_row;
                ldmx4(a[mi][0], a[mi][1], a[mi][2], a[mi][3],
                      cA + SW128B(row * 128 + (k0 + a_col) * 2));
            }
            #pragma unroll
            for (int nb = 0; nb < 2; nb++) {
                int row = warp_n * 32 + nb * 16 + b_row;
                ldmx4(b[nb][0], b[nb][1], b[nb][2], b[nb][3],
                      cB + SW128B(row * 128 + (k0 + b_col) * 2));
            }
            #pragma unroll
            for (int mi = 0; mi < 4; mi++)
                #pragma unroll
                for (int ni = 0; ni < 4; ni++)
                    mma_fp16(acc[mi][ni][0], acc[mi][ni][1],
                             acc[mi][ni][2], acc[mi][ni][3],
                             a[mi][0], a[mi][1], a[mi][2], a[mi][3],
                             b[ni >> 1][(ni & 1) * 2], b[ni >> 1][(ni & 1) * 2 + 1]);
        }
        __syncthreads();
        if (c + 3 < NCHUNK)
            gemm_issue_stage(A, B, i0, j0, c + 3, sA[buf], sB[buf], tid);
    }

    const int qrow = lane >> 2;
    const int qcol = (lane & 3) * 2;

    if (MODE == 0) {
        unsigned* hsh = (unsigned*)smem;
        hsh[tid] = 0u;
        __syncthreads();
        unsigned lastb = 0xFFFFFFFFu, cnt = 0;

        #pragma unroll
        for (int mi = 0; mi < 4; mi++) {
            int i_lo = i0 + warp_m * 64 + mi * 16 + qrow;
            int i_hi = i_lo + 8;
            float xlo = x2[i_lo], xhi = x2[i_hi];
            #pragma unroll
            for (int ni = 0; ni < 4; ni++) {
                int j = j0 + warp_n * 32 + ni * 8 + qcol;
                float yj0 = y2[j], yj1 = y2[j + 1];
                float d0 = (xlo + yj0 - 2.f * acc[mi][ni][0]) * 0.00390625f - DSHIFT;
                float d1 = (xlo + yj1 - 2.f * acc[mi][ni][1]) * 0.00390625f - DSHIFT;
                float d2v = (xhi + yj0 - 2.f * acc[mi][ni][2]) * 0.00390625f - DSHIFT;
                float d3 = (xhi + yj1 - 2.f * acc[mi][ni][3]) * 0.00390625f - DSHIFT;
                __half2 hlo = __floats2half2_rn(d0, d1);
                __half2 hhi = __floats2half2_rn(d2v, d3);
                *(__half2*)(D + (size_t)i_lo * N + j) = hlo;
                *(__half2*)(D + (size_t)i_hi * N + j) = hhi;
                unsigned short hb[4] = {
                    __half_as_ushort(__low2half(hlo)),  __half_as_ushort(__high2half(hlo)),
                    __half_as_ushort(__low2half(hhi)),  __half_as_ushort(__high2half(hhi)) };
                #pragma unroll
                for (int e = 0; e < 4; e++) {
                    unsigned bk = h2mono(hb[e]) >> 8;
                    if (bk == lastb) cnt++;
                    else {
                        if (cnt) atomicAdd(&hsh[lastb], cnt);
                        lastb = bk; cnt = 1;
                    }
                }
            }
        }
        if (cnt) atomicAdd(&hsh[lastb], cnt);
        __syncthreads();
        if (hsh[tid]) atomicAdd(&g_hist2[tid], hsh[tid]);
    } else {
        float g1 = g_gamma[0], g2 = g_gamma[1];
        float csum[4][2];
        #pragma unroll
        for (int ni = 0; ni < 4; ni++) { csum[ni][0] = 0.f; csum[ni][1] = 0.f; }

        #pragma unroll
        for (int mi = 0; mi < 4; mi++) {
            int i_lo = i0 + warp_m * 64 + mi * 16 + qrow;
            int i_hi = i_lo + 8;
            float xlo = x2[i_lo], xhi = x2[i_hi];
            float slo = 0.f, shi = 0.f;
            #pragma unroll
            for (int ni = 0; ni < 4; ni++) {
                int j = j0 + warp_n * 32 + ni * 8 + qcol;
                float yj0 = x2[j], yj1 = x2[j + 1];
                float d0 = (xlo + yj0 - 2.f * acc[mi][ni][0]) * 0.00390625f;
                float d1 = (xlo + yj1 - 2.f * acc[mi][ni][1]) * 0.00390625f;
                float d2v = (xhi + yj0 - 2.f * acc[mi][ni][2]) * 0.00390625f;
                float d3 = (xhi + yj1 - 2.f * acc[mi][ni][3]) * 0.00390625f;
                float e0 = __expf(-g1 * d0)  + __expf(-g2 * d0);
                float e1 = __expf(-g1 * d1)  + __expf(-g2 * d1);
                float e2 = __expf(-g1 * d2v) + __expf(-g2 * d2v);
                float e3 = __expf(-g1 * d3)  + __expf(-g2 * d3);
                slo += e0 + e1;
                shi += e2 + e3;
                csum[ni][0] += e0 + e2;
                csum[ni][1] += e1 + e3;
            }
            slo += __shfl_xor_sync(0xFFFFFFFFu, slo, 1);
            slo += __shfl_xor_sync(0xFFFFFFFFu, slo, 2);
            shi += __shfl_xor_sync(0xFFFFFFFFu, shi, 1);
            shi += __shfl_xor_sync(0xFFFFFFFFu, shi, 2);
            if ((lane & 3) == 0) {
                int col = tj * 4 + warp_n;
                g_selfpart[(size_t)i_lo * 128 + col] = slo;
                g_selfpart[(size_t)i_hi * 128 + col] = shi;
            }
        }
        if (ti != tj) {
            #pragma unroll
            for (int ni = 0; ni < 4; ni++) {
                #pragma unroll
                for (int cc = 0; cc < 2; cc++) {
                    float v = csum[ni][cc];
                    v += __shfl_xor_sync(0xFFFFFFFFu, v, 4);
                    v += __shfl_xor_sync(0xFFFFFFFFu, v, 8);
                    v += __shfl_xor_sync(0xFFFFFFFFu, v, 16);
                    if (lane < 4) {
                        int j = j0 + warp_n * 32 + ni * 8 + lane * 2 + cc;
                        g_selfpart2[(size_t)j * 64 + ti * 2 + warp_m] = v;
                    }
                }
            }
        }
    }
}

// ---------------------------------------------------------------------------
// 3) gamma_2 Gram: 64x64 tiles, float4 LDS, symmetric tiles, 32 K-slabs.
// ---------------------------------------------------------------------------
__global__ __launch_bounds__(256)
void d2_part_kernel() {
    int p = blockIdx.x;
    int ti = 0, rem = p;
    while (rem >= 4 - ti) { rem -= 4 - ti; ti++; }
    int tj = ti + rem;
    const int i0 = ti * 64, j0 = tj * 64;
    const int k0 = blockIdx.y * (N / NSLAB);

    __shared__ float Ei[32][64];
    __shared__ float Ej[32][64];
    const int tid = threadIdx.x;
    const int tx = tid & 15, ty = tid >> 4;

    float acc[4][4] = {};

    for (int kc = k0; kc < k0 + (N / NSLAB); kc += 32) {
        #pragma unroll
        for (int q = 0; q < 2; q++) {
            int idx = tid + q * 256;
            int kk = idx >> 4, c4 = (idx & 15) * 4;
            *(float4*)&Ei[kk][c4] =
                *(const float4*)&g_esa[(size_t)(kc + kk) * DIM + i0 + c4];
            *(float4*)&Ej[kk][c4] =
                *(const float4*)&g_esa[(size_t)(kc + kk) * DIM + j0 + c4];
        }
        __syncthreads();
        #pragma unroll
        for (int kk = 0; kk < 32; kk++) {
            float4 a = *(float4*)&Ei[kk][ty * 4];
            float4 b = *(float4*)&Ej[kk][tx * 4];
            acc[0][0] += a.x * b.x; acc[0][1] += a.x * b.y;
            acc[0][2] += a.x * b.z; acc[0][3] += a.x * b.w;
            acc[1][0] += a.y * b.x; acc[1][1] += a.y * b.y;
            acc[1][2] += a.y * b.z; acc[1][3] += a.y * b.w;
            acc[2][0] += a.z * b.x; acc[2][1] += a.z * b.y;
            acc[2][2] += a.z * b.z; acc[2][3] += a.z * b.w;
            acc[3][0] += a.w * b.x; acc[3][1] += a.w * b.y;
            acc[3][2] += a.w * b.z; acc[3][3] += a.w * b.w;
        }
        __syncthreads();
    }

    float* P = g_D2p + (size_t)blockIdx.y * DIM * DIM;
    #pragma unroll
    for (int r = 0; r < 4; r++) {
        #pragma unroll
        for (int c = 0; c < 4; c++)
            P[(size_t)(i0 + ty * 4 + r) * DIM + j0 + tx * 4 + c] = acc[r][c];
    }
}

__global__ void d2_final_kernel() {
    int i = blockIdx.x, t = threadIdx.x;
    __shared__ float diag[256];
    float dsum = 0.f;
    #pragma unroll
    for (int z = 0; z < NSLAB; z++)
        dsum += g_D2p[(size_t)z * DIM * DIM + t * DIM + t];
    diag[t] = dsum;
    size_t idx = ((i >> 6) <= (t >> 6)) ? (size_t)i * DIM + t
                                        : (size_t)t * DIM + i;
    float s = 0.f;
    #pragma unroll
    for (int z = 0; z < NSLAB; z++)
        s += g_D2p[(size_t)z * DIM * DIM + idx];
    __syncthreads();
    g_D2[i * DIM + t] = (diag[i] + diag[t] - 2.f * s) * (1.f / 4096.f);
}

// ---------------------------------------------------------------------------
// 4a) D2 median + gamma_2: one single-block kernel (fp32 data, 4 passes)
// ---------------------------------------------------------------------------
__global__ __launch_bounds__(1024)
void d2_median_kernel() {
    __shared__ unsigned hist[256];
    __shared__ unsigned s[256];
    __shared__ unsigned sh_prefix, sh_k;
    int t = threadIdx.x;
    if (t == 0) { sh_prefix = 0u; sh_k = (DIM * DIM - 1) / 2; }
    __syncthreads();
    #pragma unroll
    for (int pass = 0; pass < 4; pass++) {
        if (t < 256) hist[t] = 0u;
        __syncthreads();
        int shift = 24 - pass * 8;
        unsigned prefix = sh_prefix;
        for (int i = t; i < DIM * DIM; i += 1024) {
            unsigned u = f2u_mono(g_D2[i]);
            bool ok = (pass == 0) || ((u >> (shift + 8)) == prefix);
            if (ok) atomicAdd(&hist[(u >> shift) & 0xFFu], 1u);
        }
        __syncthreads();
        unsigned kcur = sh_k;
        if (t < 256) s[t] = hist[t];
        __syncthreads();
        for (int off = 1; off < 256; off <<= 1) {
            unsigned v = (t < 256 && t >= off) ? s[t - off] : 0u;
            __syncthreads();
            if (t < 256) s[t] += v;
            __syncthreads();
        }
        if (t < 256) {
            unsigned c = hist[t];
            unsigned incl = s[t], excl = incl - c;
            if (kcur >= excl && kcur < incl) {
                sh_k = kcur - excl;
                sh_prefix = (prefix << 8) | (unsigned)t;
            }
        }
        __syncthreads();
    }
    if (t == 0) {
        unsigned u = sh_prefix;
        unsigned bits = (u & 0x80000000u) ? (u ^ 0x80000000u) : ~u;
        g_median[1] = __uint_as_float(bits);
        g_gamma[1]  = 1.0f / (__uint_as_float(bits) + EPS);
    }
}

// ---------------------------------------------------------------------------
// 4b) D median (16-bit shifted fp16 keys):
//     pass 0 (top byte) fused in GEMM1 -> g_hist2[0]
//     pass 1 (low byte): one scan of fp16 D -> g_hist2[1]; finalize -> gamma_1
// ---------------------------------------------------------------------------
__device__ __forceinline__ void chain_prefix2(int npass, unsigned& prefix_out,
                                              unsigned* s, unsigned* sh2) {
    int t = threadIdx.x;
    if (t == 0) { sh2[0] = 0u; sh2[1] = K_TARGET; }
    __syncthreads();
    for (int q = 0; q < npass; q++) {
        unsigned c = g_hist2[q * 256 + t];
        unsigned kcur = sh2[1];
        unsigned pfx  = sh2[0];
        __syncthreads();
        s[t] = c;
        __syncthreads();
        for (int off = 1; off < 256; off <<= 1) {
            unsigned v = (t >= off) ? s[t - off] : 0u;
            __syncthreads();
            s[t] += v;
            __syncthreads();
        }
        unsigned incl = s[t], excl = incl - c;
        if (kcur >= excl && kcur < incl) {
            sh2[1] = kcur - excl;
            sh2[0] = (pfx << 8) | (unsigned)t;
        }
        __syncthreads();
    }
    prefix_out = sh2[0];
}

__global__ __launch_bounds__(256)
void select_hist_low(const __half* __restrict__ data, unsigned n8) {
    __shared__ unsigned s[256];
    __shared__ unsigned sh2[2];
    __shared__ unsigned hloc[256];
    unsigned prefix8;
    chain_prefix2(1, prefix8, s, sh2);

    hloc[threadIdx.x] = 0u;
    __syncthreads();
    unsigned stride = gridDim.x * blockDim.x;
    int lane = threadIdx.x & 31;
    const uint4* d8 = (const uint4*)data;
    for (unsigned base = blockIdx.x * blockDim.x; base < n8; base += stride) {
        unsigned i = base + threadIdx.x;
        uint4 v = make_uint4(0u, 0u, 0u, 0u);
        bool valid = (i < n8);
        if (valid) v = d8[i];
        unsigned words[4] = {v.x, v.y, v.z, v.w};
        #pragma unroll
        for (int w = 0; w < 4; w++) {
            #pragma unroll
            for (int hh = 0; hh < 2; hh++) {
                unsigned bucket = 0xFFFFFFFFu;
                if (valid) {
                    unsigned short hb = (unsigned short)(words[w] >> (hh * 16));
                    unsigned key = h2mono(hb);
                    if ((key >> 8) == prefix8) bucket = key & 0xFFu;
                }
                unsigned m = __match_any_sync(0xFFFFFFFFu, bucket);
                if (bucket != 0xFFFFFFFFu && lane == __ffs(m) - 1)
                    atomicAdd(&hloc[bucket], (unsigned)__popc(m));
            }
        }
    }
    __syncthreads();
    if (hloc[threadIdx.x])
        atomicAdd(&g_hist2[256 + threadIdx.x], hloc[threadIdx.x]);
}

__global__ __launch_bounds__(256)
void select_finalize16() {
    __shared__ unsigned s[256];
    __shared__ unsigned sh2[2];
    unsigned prefix16;
    chain_prefix2(2, prefix16, s, sh2);
    if (threadIdx.x == 0) {
        unsigned key = prefix16 & 0xFFFFu;
        unsigned short bits = (key & 0x8000u) ? (unsigned short)(key ^ 0x8000u)
                                              : (unsigned short)~key;
        float med = __half2float(__ushort_as_half(bits)) + DSHIFT;
        g_median[0] = med;
        g_gamma[0]  = 1.0f / (med + EPS);
    }
}

// ---------------------------------------------------------------------------
// 5) Row means of exp over stored fp16 (d-2) (agent-expert pass)
// ---------------------------------------------------------------------------
__global__ __launch_bounds__(256)
void rowsum_kernel(const __half* __restrict__ D) {
    int i = blockIdx.x, t = threadIdx.x;
    float g1 = g_gamma[0], g2 = g_gamma[1];
    const uint4* row = (const uint4*)(D + (size_t)i * N);
    float s = 0.f;
    #pragma unroll 2
    for (int j = t; j < N / 8; j += 256) {
        uint4 v = row[j];
        unsigned words[4] = {v.x, v.y, v.z, v.w};
        #pragma unroll
        for (int w = 0; w < 4; w++) {
            float2 p = __half22float2(*(__half2*)&words[w]);
            float da = p.x + DSHIFT, db = p.y + DSHIFT;
            s += __expf(-g1 * da) + __expf(-g2 * da)
               + __expf(-g1 * db) + __expf(-g2 * db);
        }
    }
    __shared__ float sh[256];
    sh[t] = s;
    __syncthreads();
    #pragma unroll
    for (int k = 128; k > 0; k >>= 1) {
        if (t < k) sh[t] += sh[t + k];
        __syncthreads();
    }
    if (t == 0) g_sim[i] = sh[0] * (1.0f / (float)N);
}

// ---------------------------------------------------------------------------
// 6) final: out[i] = g_sim[i] - mean of valid self partials
// ---------------------------------------------------------------------------
__global__ void self_final_kernel(float* __restrict__ out) {
    int i = blockIdx.x * blockDim.x + threadIdx.x;
    int t = i >> 7;
    const float* rp = g_selfpart  + (size_t)i * 128;
    const float* cp = g_selfpart2 + (size_t)i * 64;
    float s = 0.f;
    for (int b = 4 * t; b < 128; b++) s += rp[b];
    for (int b = 0; b < 2 * t; b++)  s += cp[b];
    out[i] = g_sim[i] - s * (1.0f / (float)N);
}

// ---------------------------------------------------------------------------
// Host orchestration (graph-capturable)
// ---------------------------------------------------------------------------
extern "C" void kernel_launch(void* const* d_in, const int* in_sizes, int n_in,
                              void* d_out, int out_size) {
    const float* state   = (const float*)d_in[0];
    const float* action  = (const float*)d_in[1];
    const float* estate  = (const float*)d_in[2];
    const float* eaction = (const float*)d_in[3];
    float* out = (float*)d_out;

    float *p_esa, *p_x2, *p_y2;
    __half *p_D, *p_HA, *p_HB;
    cudaGetSymbolAddress((void**)&p_esa, g_esa);
    cudaGetSymbolAddress((void**)&p_x2,  g_x2);
    cudaGetSymbolAddress((void**)&p_y2,  g_y2);
    cudaGetSymbolAddress((void**)&p_D,   g_D);
    cudaGetSymbolAddress((void**)&p_HA,  g_HA);
    cudaGetSymbolAddress((void**)&p_HB,  g_HB);

    cudaFuncSetAttribute(hmma_dist_gemm<0>,
                         cudaFuncAttributeMaxDynamicSharedMemorySize, GM_SMEM);
    cudaFuncSetAttribute(hmma_dist_gemm<1>,
                         cudaFuncAttributeMaxDynamicSharedMemorySize, GM_SMEM);

    // 1) concat + norms + fp16 copies (also zeroes g_hist2)
    prep_kernel<<<N, 256>>>(state,  action,  nullptr, p_x2, p_HA);
    prep_kernel<<<N, 256>>>(estate, eaction, p_esa,   p_y2, p_HB);

    // 2) D_agent_expert (fp16 shifted D) + fused top-byte histogram
    dim3 ggrid(N / 128, N / 128);
    hmma_dist_gemm<0><<<ggrid, 256, GM_SMEM>>>(p_HA, p_HB, p_x2, p_y2, p_D);

    // 3) gamma_2 matrix + single-launch median
    d2_part_kernel<<<dim3(10, NSLAB), 256>>>();
    d2_final_kernel<<<DIM, DIM>>>();
    d2_median_kernel<<<1, 1024>>>();

    // 4) D median: one low-byte scan + finalize/gamma_1
    {
        unsigned n8 = ((unsigned)N * (unsigned)N) / 8u;
        select_hist_low<<<2048, 256>>>(p_D, n8);
        select_finalize16<<<1, 256>>>();
    }

    // 5) agent-expert similarity means from stored shifted fp16 D
    rowsum_kernel<<<N, 256>>>(p_D);

    // 6) self-distance GEMM: fp16, triangular, fused row+col sums
    hmma_dist_gemm<1><<<NTRI, 256, GM_SMEM>>>(p_HA, p_HA, p_x2, p_x2, nullptr);
    self_final_kernel<<<N / 256, 256>>>(out);
}

// round 17
// speedup vs baseline: 2.5437x; 1.0541x over previous
#include <cuda_runtime.h>
#include <cuda_fp16.h>
#include <cstdint>
#include <cmath>

// ---------------------------------------------------------------------------
// Shapes: n1 = n2 = 4096, s = 192, a = 64, d = 256. fp16 GEMMs.
// D stored as fp16 of (d - 2.0): distances concentrate at d~2, so shifting
// centers the fp16 binade on the data (ulp 2^-12 vs 2^-9 unshifted).
// Graph: fork d2/gamma_2 branch onto a second captured stream.
// ---------------------------------------------------------------------------
#define N      4096
#define DIM    256
#define SDIM   192
#define ADIM   64
#define EPS    1e-8f
#define NSLAB  32
#define DSHIFT 2.0f

// ---------------------------------------------------------------------------
// Scratch (device globals — allocations forbidden)
// ---------------------------------------------------------------------------
__device__ __align__(256) float  g_esa[N * DIM];               // expert fp32 (d2 path)
__device__ __align__(256) float  g_x2 [N];
__device__ __align__(256) float  g_y2 [N];
__device__ __align__(256) __half g_D  [(size_t)N * N];         // 32 MB fp16 (d-2)
__device__ __align__(256) float  g_D2 [DIM * DIM];
__device__ __align__(256) float  g_D2p[NSLAB * DIM * DIM];
__device__ __align__(256) float  g_sim[N];
__device__ __align__(256) float  g_selfpart [(size_t)N * 128]; // row-sum slots
__device__ __align__(256) float  g_selfpart2[(size_t)N * 64];  // col-sum slots
__device__ __align__(256) __half g_HA[(size_t)N * DIM];        // sa  fp16
__device__ __align__(256) __half g_HB[(size_t)N * DIM];        // esa fp16
__device__ unsigned g_hist2[2 * 256];  // pass-0 (fused) + pass-1 histograms
__device__ float    g_median[2];
__device__ float    g_gamma[2];

#define K_TARGET 8388607u   // (N*N - 1) / 2

// ---------------------------------------------------------------------------
// helpers
// ---------------------------------------------------------------------------
__device__ __forceinline__ uint32_t smem_u32(const void* p) {
    uint32_t a;
    asm("{ .reg .u64 t; cvta.to.shared.u64 t, %1; cvt.u32.u64 %0, t; }"
        : "=r"(a) : "l"(p));
    return a;
}
#define SW128B(o) ((o) ^ (((o) >> 3) & 0x70))

__device__ __forceinline__ void cp_async16(uint32_t sdst, const void* gsrc) {
    asm volatile("cp.async.cg.shared.global [%0], [%1], 16;"
                 :: "r"(sdst), "l"(gsrc) : "memory");
}
__device__ __forceinline__ void cp_commit() {
    asm volatile("cp.async.commit_group;" ::: "memory");
}
__device__ __forceinline__ void ldmx4(uint32_t& r0, uint32_t& r1,
                                      uint32_t& r2, uint32_t& r3, uint32_t addr) {
    asm volatile("ldmatrix.sync.aligned.m8n8.x4.shared.b16 {%0,%1,%2,%3}, [%4];"
                 : "=r"(r0), "=r"(r1), "=r"(r2), "=r"(r3) : "r"(addr));
}
__device__ __forceinline__ void mma_fp16(float& c0, float& c1, float& c2, float& c3,
                                         uint32_t a0, uint32_t a1, uint32_t a2, uint32_t a3,
                                         uint32_t b0, uint32_t b1) {
    asm volatile(
        "mma.sync.aligned.m16n8k16.row.col.f32.f16.f16.f32 "
        "{%0,%1,%2,%3}, {%4,%5,%6,%7}, {%8,%9}, {%0,%1,%2,%3};"
        : "+f"(c0), "+f"(c1), "+f"(c2), "+f"(c3)
        : "r"(a0), "r"(a1), "r"(a2), "r"(a3), "r"(b0), "r"(b1));
}
// 16-bit monotone key for fp16
__device__ __forceinline__ unsigned h2mono(unsigned short b) {
    return (b & 0x8000u) ? (unsigned)(unsigned short)~b
                         : (unsigned)(b | 0x8000u);
}
__device__ __forceinline__ unsigned f2u_mono(float f) {
    unsigned b = __float_as_uint(f);
    return (b & 0x80000000u) ? ~b : (b | 0x80000000u);
}

// ---------------------------------------------------------------------------
// 1) concat + norm + fp16 copy, fused. Zeroes g_hist2.
// ---------------------------------------------------------------------------
__global__ void prep_kernel(const float* __restrict__ st,
                            const float* __restrict__ ac,
                            float* __restrict__ cat, float* __restrict__ nrm,
                            __half* __restrict__ dstH) {
    int row = blockIdx.x, t = threadIdx.x;
    if (blockIdx.x < 2) g_hist2[blockIdx.x * 256 + t] = 0u;
    float v = (t < SDIM) ? st[row * SDIM + t] : ac[row * ADIM + (t - SDIM)];
    if (cat) cat[row * DIM + t] = v;
    dstH[(size_t)row * DIM + t] = __float2half(v);

    __shared__ float sh[256];
    sh[t] = v * v;
    __syncthreads();
    #pragma unroll
    for (int s = 128; s > 0; s >>= 1) {
        if (t < s) sh[t] += sh[t + s];
        __syncthreads();
    }
    if (t == 0) nrm[row] = sh[0];
}

// ---------------------------------------------------------------------------
// 2) HMMA distance GEMM — fp16, K=256 (4 chunks of BK=64), 128x128 CTA tile,
//    8 warps (2x4) of 64x32, 3-stage cp.async, SW128 smem, 2 CTAs/SM.
//    MODE 0: full grid; store fp16 (d-2) + fused top-byte histogram.
//    MODE 1: triangular grid (528 tiles); fused self row+col exp-sums, no D.
// ---------------------------------------------------------------------------
#define BK        64
#define TILE_B    (128 * BK * 2)
#define STG       (2 * TILE_B)
#define GM_SMEM   (3 * STG)               // 96 KB
#define NCHUNK    4
#define NTILE     32
#define NTRI      (NTILE * (NTILE + 1) / 2)

__device__ __forceinline__ void gemm_issue_stage(
    const __half* __restrict__ A, const __half* __restrict__ B,
    int i0, int j0, int c, uint32_t sA, uint32_t sB, int tid)
{
    const __half* Ap = A + (size_t)i0 * DIM + c * BK;
    const __half* Bp = B + (size_t)j0 * DIM + c * BK;
    #pragma unroll
    for (int q = 0; q < 4; q++) {
        int idx = tid + q * 256;
        int row = idx >> 3, seg = idx & 7;
        cp_async16(sA + SW128B(row * 128 + seg * 16),
                   Ap + (size_t)row * DIM + seg * 8);
    }
    #pragma unroll
    for (int q = 0; q < 4; q++) {
        int idx = tid + q * 256;
        int row = idx >> 3, seg = idx & 7;
        cp_async16(sB + SW128B(row * 128 + seg * 16),
                   Bp + (size_t)row * DIM + seg * 8);
    }
    cp_commit();
}

template <int MODE>
__global__ __launch_bounds__(256, 2)
void hmma_dist_gemm(const __half* __restrict__ A,
                    const __half* __restrict__ B,
                    const float* __restrict__ x2,
                    const float* __restrict__ y2,
                    __half* __restrict__ D)
{
    extern __shared__ char smem[];
    const uint32_t sb = smem_u32(smem);
    const int tid = threadIdx.x;
    const int wid = tid >> 5, lane = tid & 31;
    const int warp_m = wid >> 2, warp_n = wid & 3;

    int ti, tj;
    if (MODE == 1) {
        int bid = blockIdx.x;
        ti = (int)(32.5f - sqrtf(32.5f * 32.5f - 2.0f * (float)bid));
        while (NTILE * ti - ti * (ti - 1) / 2 > bid) ti--;
        while (NTILE * (ti + 1) - (ti + 1) * ti / 2 <= bid) ti++;
        tj = ti + (bid - (NTILE * ti - ti * (ti - 1) / 2));
    } else {
        ti = blockIdx.y;
        tj = blockIdx.x;
    }
    const int i0 = ti * 128;
    const int j0 = tj * 128;

    uint32_t sA[3] = { sb,           sb + STG,           sb + 2 * STG };
    uint32_t sB[3] = { sb + TILE_B,  sb + STG + TILE_B,  sb + 2 * STG + TILE_B };

    float acc[4][4][4];
    #pragma unroll
    for (int mi = 0; mi < 4; mi++)
        #pragma unroll
        for (int ni = 0; ni < 4; ni++)
            #pragma unroll
            for (int e = 0; e < 4; e++) acc[mi][ni][e] = 0.f;

    gemm_issue_stage(A, B, i0, j0, 0, sA[0], sB[0], tid);
    gemm_issue_stage(A, B, i0, j0, 1, sA[1], sB[1], tid);
    gemm_issue_stage(A, B, i0, j0, 2, sA[2], sB[2], tid);

    const int a_row = (lane & 15);
    const int a_col = (lane & 16) ? 8 : 0;
    const int b_row = (lane & 7) + ((lane & 16) >> 1);
    const int b_col = (lane & 8) ? 8 : 0;

    for (int c = 0; c < NCHUNK; c++) {
        if (c < NCHUNK - 2)      asm volatile("cp.async.wait_group 2;" ::: "memory");
        else if (c < NCHUNK - 1) asm volatile("cp.async.wait_group 1;" ::: "memory");
        else                     asm volatile("cp.async.wait_group 0;" ::: "memory");
        __syncthreads();

        int buf = c % 3;
        uint32_t cA = sA[buf], cB = sB[buf];
        #pragma unroll
        for (int ks = 0; ks < BK / 16; ks++) {
            int k0 = ks * 16;
            uint32_t a[4][4], b[2][4];
            #pragma unroll
            for (int mi = 0; mi < 4; mi++) {
                int row = warp_m * 64 + mi * 16 + a_row;
                ldmx4(a[mi][0], a[mi][1], a[mi][2], a[mi][3],
                      cA + SW128B(row * 128 + (k0 + a_col) * 2));
            }
            #pragma unroll
            for (int nb = 0; nb < 2; nb++) {
                int row = warp_n * 32 + nb * 16 + b_row;
                ldmx4(b[nb][0], b[nb][1], b[nb][2], b[nb][3],
                      cB + SW128B(row * 128 + (k0 + b_col) * 2));
            }
            #pragma unroll
            for (int mi = 0; mi < 4; mi++)
                #pragma unroll
                for (int ni = 0; ni < 4; ni++)
                    mma_fp16(acc[mi][ni][0], acc[mi][ni][1],
                             acc[mi][ni][2], acc[mi][ni][3],
                             a[mi][0], a[mi][1], a[mi][2], a[mi][3],
                             b[ni >> 1][(ni & 1) * 2], b[ni >> 1][(ni & 1) * 2 + 1]);
        }
        __syncthreads();
        if (c + 3 < NCHUNK)
            gemm_issue_stage(A, B, i0, j0, c + 3, sA[buf], sB[buf], tid);
    }

    const int qrow = lane >> 2;
    const int qcol = (lane & 3) * 2;

    if (MODE == 0) {
        unsigned* hsh = (unsigned*)smem;
        hsh[tid] = 0u;
        __syncthreads();
        unsigned lastb = 0xFFFFFFFFu, cnt = 0;

        #pragma unroll
        for (int mi = 0; mi < 4; mi++) {
            int i_lo = i0 + warp_m * 64 + mi * 16 + qrow;
            int i_hi = i_lo + 8;
            float xlo = x2[i_lo], xhi = x2[i_hi];
            #pragma unroll
            for (int ni = 0; ni < 4; ni++) {
                int j = j0 + warp_n * 32 + ni * 8 + qcol;
                float yj0 = y2[j], yj1 = y2[j + 1];
                float d0 = (xlo + yj0 - 2.f * acc[mi][ni][0]) * 0.00390625f - DSHIFT;
                float d1 = (xlo + yj1 - 2.f * acc[mi][ni][1]) * 0.00390625f - DSHIFT;
                float d2v = (xhi + yj0 - 2.f * acc[mi][ni][2]) * 0.00390625f - DSHIFT;
                float d3 = (xhi + yj1 - 2.f * acc[mi][ni][3]) * 0.00390625f - DSHIFT;
                __half2 hlo = __floats2half2_rn(d0, d1);
                __half2 hhi = __floats2half2_rn(d2v, d3);
                *(__half2*)(D + (size_t)i_lo * N + j) = hlo;
                *(__half2*)(D + (size_t)i_hi * N + j) = hhi;
                unsigned short hb[4] = {
                    __half_as_ushort(__low2half(hlo)),  __half_as_ushort(__high2half(hlo)),
                    __half_as_ushort(__low2half(hhi)),  __half_as_ushort(__high2half(hhi)) };
                #pragma unroll
                for (int e = 0; e < 4; e++) {
                    unsigned bk = h2mono(hb[e]) >> 8;
                    if (bk == lastb) cnt++;
                    else {
                        if (cnt) atomicAdd(&hsh[lastb], cnt);
                        lastb = bk; cnt = 1;
                    }
                }
            }
        }
        if (cnt) atomicAdd(&hsh[lastb], cnt);
        __syncthreads();
        if (hsh[tid]) atomicAdd(&g_hist2[tid], hsh[tid]);
    } else {
        float g1 = g_gamma[0], g2 = g_gamma[1];
        float csum[4][2];
        #pragma unroll
        for (int ni = 0; ni < 4; ni++) { csum[ni][0] = 0.f; csum[ni][1] = 0.f; }

        #pragma unroll
        for (int mi = 0; mi < 4; mi++) {
            int i_lo = i0 + warp_m * 64 + mi * 16 + qrow;
            int i_hi = i_lo + 8;
            float xlo = x2[i_lo], xhi = x2[i_hi];
            float slo = 0.f, shi = 0.f;
            #pragma unroll
            for (int ni = 0; ni < 4; ni++) {
                int j = j0 + warp_n * 32 + ni * 8 + qcol;
                float yj0 = x2[j], yj1 = x2[j + 1];
                float d0 = (xlo + yj0 - 2.f * acc[mi][ni][0]) * 0.00390625f;
                float d1 = (xlo + yj1 - 2.f * acc[mi][ni][1]) * 0.00390625f;
                float d2v = (xhi + yj0 - 2.f * acc[mi][ni][2]) * 0.00390625f;
                float d3 = (xhi + yj1 - 2.f * acc[mi][ni][3]) * 0.00390625f;
                float e0 = __expf(-g1 * d0)  + __expf(-g2 * d0);
                float e1 = __expf(-g1 * d1)  + __expf(-g2 * d1);
                float e2 = __expf(-g1 * d2v) + __expf(-g2 * d2v);
                float e3 = __expf(-g1 * d3)  + __expf(-g2 * d3);
                slo += e0 + e1;
                shi += e2 + e3;
                csum[ni][0] += e0 + e2;
                csum[ni][1] += e1 + e3;
            }
            slo += __shfl_xor_sync(0xFFFFFFFFu, slo, 1);
            slo += __shfl_xor_sync(0xFFFFFFFFu, slo, 2);
            shi += __shfl_xor_sync(0xFFFFFFFFu, shi, 1);
            shi += __shfl_xor_sync(0xFFFFFFFFu, shi, 2);
            if ((lane & 3) == 0) {
                int col = tj * 4 + warp_n;
                g_selfpart[(size_t)i_lo * 128 + col] = slo;
                g_selfpart[(size_t)i_hi * 128 + col] = shi;
            }
        }
        if (ti != tj) {
            #pragma unroll
            for (int ni = 0; ni < 4; ni++) {
                #pragma unroll
                for (int cc = 0; cc < 2; cc++) {
                    float v = csum[ni][cc];
                    v += __shfl_xor_sync(0xFFFFFFFFu, v, 4);
                    v += __shfl_xor_sync(0xFFFFFFFFu, v, 8);
                    v += __shfl_xor_sync(0xFFFFFFFFu, v, 16);
                    if (lane < 4) {
                        int j = j0 + warp_n * 32 + ni * 8 + lane * 2 + cc;
                        g_selfpart2[(size_t)j * 64 + ti * 2 + warp_m] = v;
                    }
                }
            }
        }
    }
}

// ---------------------------------------------------------------------------
// 3) gamma_2 Gram: 64x64 tiles, float4 LDS, symmetric tiles, 32 K-slabs.
// ---------------------------------------------------------------------------
__global__ __launch_bounds__(256)
void d2_part_kernel() {
    int p = blockIdx.x;
    int ti = 0, rem = p;
    while (rem >= 4 - ti) { rem -= 4 - ti; ti++; }
    int tj = ti + rem;
    const int i0 = ti * 64, j0 = tj * 64;
    const int k0 = blockIdx.y * (N / NSLAB);

    __shared__ float Ei[32][64];
    __shared__ float Ej[32][64];
    const int tid = threadIdx.x;
    const int tx = tid & 15, ty = tid >> 4;

    float acc[4][4] = {};

    for (int kc = k0; kc < k0 + (N / NSLAB); kc += 32) {
        #pragma unroll
        for (int q = 0; q < 2; q++) {
            int idx = tid + q * 256;
            int kk = idx >> 4, c4 = (idx & 15) * 4;
            *(float4*)&Ei[kk][c4] =
                *(const float4*)&g_esa[(size_t)(kc + kk) * DIM + i0 + c4];
            *(float4*)&Ej[kk][c4] =
                *(const float4*)&g_esa[(size_t)(kc + kk) * DIM + j0 + c4];
        }
        __syncthreads();
        #pragma unroll
        for (int kk = 0; kk < 32; kk++) {
            float4 a = *(float4*)&Ei[kk][ty * 4];
            float4 b = *(float4*)&Ej[kk][tx * 4];
            acc[0][0] += a.x * b.x; acc[0][1] += a.x * b.y;
            acc[0][2] += a.x * b.z; acc[0][3] += a.x * b.w;
            acc[1][0] += a.y * b.x; acc[1][1] += a.y * b.y;
            acc[1][2] += a.y * b.z; acc[1][3] += a.y * b.w;
            acc[2][0] += a.z * b.x; acc[2][1] += a.z * b.y;
            acc[2][2] += a.z * b.z; acc[2][3] += a.z * b.w;
            acc[3][0] += a.w * b.x; acc[3][1] += a.w * b.y;
            acc[3][2] += a.w * b.z; acc[3][3] += a.w * b.w;
        }
        __syncthreads();
    }

    float* P = g_D2p + (size_t)blockIdx.y * DIM * DIM;
    #pragma unroll
    for (int r = 0; r < 4; r++) {
        #pragma unroll
        for (int c = 0; c < 4; c++)
            P[(size_t)(i0 + ty * 4 + r) * DIM + j0 + tx * 4 + c] = acc[r][c];
    }
}

__global__ void d2_final_kernel() {
    int i = blockIdx.x, t = threadIdx.x;
    __shared__ float diag[256];
    float dsum = 0.f;
    #pragma unroll
    for (int z = 0; z < NSLAB; z++)
        dsum += g_D2p[(size_t)z * DIM * DIM + t * DIM + t];
    diag[t] = dsum;
    size_t idx = ((i >> 6) <= (t >> 6)) ? (size_t)i * DIM + t
                                        : (size_t)t * DIM + i;
    float s = 0.f;
    #pragma unroll
    for (int z = 0; z < NSLAB; z++)
        s += g_D2p[(size_t)z * DIM * DIM + idx];
    __syncthreads();
    g_D2[i * DIM + t] = (diag[i] + diag[t] - 2.f * s) * (1.f / 4096.f);
}

// ---------------------------------------------------------------------------
// 4a) D2 median + gamma_2: one single-block kernel (fp32 data, 4 passes)
// ---------------------------------------------------------------------------
__global__ __launch_bounds__(1024)
void d2_median_kernel() {
    __shared__ unsigned hist[256];
    __shared__ unsigned s[256];
    __shared__ unsigned sh_prefix, sh_k;
    int t = threadIdx.x;
    if (t == 0) { sh_prefix = 0u; sh_k = (DIM * DIM - 1) / 2; }
    __syncthreads();
    #pragma unroll
    for (int pass = 0; pass < 4; pass++) {
        if (t < 256) hist[t] = 0u;
        __syncthreads();
        int shift = 24 - pass * 8;
        unsigned prefix = sh_prefix;
        for (int i = t; i < DIM * DIM; i += 1024) {
            unsigned u = f2u_mono(g_D2[i]);
            bool ok = (pass == 0) || ((u >> (shift + 8)) == prefix);
            if (ok) atomicAdd(&hist[(u >> shift) & 0xFFu], 1u);
        }
        __syncthreads();
        unsigned kcur = sh_k;
        if (t < 256) s[t] = hist[t];
        __syncthreads();
        for (int off = 1; off < 256; off <<= 1) {
            unsigned v = (t < 256 && t >= off) ? s[t - off] : 0u;
            __syncthreads();
            if (t < 256) s[t] += v;
            __syncthreads();
        }
        if (t < 256) {
            unsigned c = hist[t];
            unsigned incl = s[t], excl = incl - c;
            if (kcur >= excl && kcur < incl) {
                sh_k = kcur - excl;
                sh_prefix = (prefix << 8) | (unsigned)t;
            }
        }
        __syncthreads();
    }
    if (t == 0) {
        unsigned u = sh_prefix;
        unsigned bits = (u & 0x80000000u) ? (u ^ 0x80000000u) : ~u;
        g_median[1] = __uint_as_float(bits);
        g_gamma[1]  = 1.0f / (__uint_as_float(bits) + EPS);
    }
}

// ---------------------------------------------------------------------------
// 4b) D median (16-bit shifted fp16 keys):
//     pass 0 (top byte) fused in GEMM1 -> g_hist2[0]
//     pass 1 (low byte): one scan of fp16 D -> g_hist2[1]; finalize -> gamma_1
// ---------------------------------------------------------------------------
__device__ __forceinline__ void chain_prefix2(int npass, unsigned& prefix_out,
                                              unsigned* s, unsigned* sh2) {
    int t = threadIdx.x;
    if (t == 0) { sh2[0] = 0u; sh2[1] = K_TARGET; }
    __syncthreads();
    for (int q = 0; q < npass; q++) {
        unsigned c = g_hist2[q * 256 + t];
        unsigned kcur = sh2[1];
        unsigned pfx  = sh2[0];
        __syncthreads();
        s[t] = c;
        __syncthreads();
        for (int off = 1; off < 256; off <<= 1) {
            unsigned v = (t >= off) ? s[t - off] : 0u;
            __syncthreads();
            s[t] += v;
            __syncthreads();
        }
        unsigned incl = s[t], excl = incl - c;
        if (kcur >= excl && kcur < incl) {
            sh2[1] = kcur - excl;
            sh2[0] = (pfx << 8) | (unsigned)t;
        }
        __syncthreads();
    }
    prefix_out = sh2[0];
}

__global__ __launch_bounds__(256)
void select_hist_low(const __half* __restrict__ data, unsigned n8) {
    __shared__ unsigned s[256];
    __shared__ unsigned sh2[2];
    __shared__ unsigned hloc[256];
    unsigned prefix8;
    chain_prefix2(1, prefix8, s, sh2);

    hloc[threadIdx.x] = 0u;
    __syncthreads();
    unsigned stride = gridDim.x * blockDim.x;
    int lane = threadIdx.x & 31;
    const uint4* d8 = (const uint4*)data;
    for (unsigned base = blockIdx.x * blockDim.x; base < n8; base += stride) {
        unsigned i = base + threadIdx.x;
        uint4 v = make_uint4(0u, 0u, 0u, 0u);
        bool valid = (i < n8);
        if (valid) v = d8[i];
        unsigned words[4] = {v.x, v.y, v.z, v.w};
        #pragma unroll
        for (int w = 0; w < 4; w++) {
            #pragma unroll
            for (int hh = 0; hh < 2; hh++) {
                unsigned bucket = 0xFFFFFFFFu;
                if (valid) {
                    unsigned short hb = (unsigned short)(words[w] >> (hh * 16));
                    unsigned key = h2mono(hb);
                    if ((key >> 8) == prefix8) bucket = key & 0xFFu;
                }
                unsigned m = __match_any_sync(0xFFFFFFFFu, bucket);
                if (bucket != 0xFFFFFFFFu && lane == __ffs(m) - 1)
                    atomicAdd(&hloc[bucket], (unsigned)__popc(m));
            }
        }
    }
    __syncthreads();
    if (hloc[threadIdx.x])
        atomicAdd(&g_hist2[256 + threadIdx.x], hloc[threadIdx.x]);
}

__global__ __launch_bounds__(256)
void select_finalize16() {
    __shared__ unsigned s[256];
    __shared__ unsigned sh2[2];
    unsigned prefix16;
    chain_prefix2(2, prefix16, s, sh2);
    if (threadIdx.x == 0) {
        unsigned key = prefix16 & 0xFFFFu;
        unsigned short bits = (key & 0x8000u) ? (unsigned short)(key ^ 0x8000u)
                                              : (unsigned short)~key;
        float med = __half2float(__ushort_as_half(bits)) + DSHIFT;
        g_median[0] = med;
        g_gamma[0]  = 1.0f / (med + EPS);
    }
}

// ---------------------------------------------------------------------------
// 5) Row means of exp over stored fp16 (d-2) (agent-expert pass)
// ---------------------------------------------------------------------------
__global__ __launch_bounds__(256)
void rowsum_kernel(const __half* __restrict__ D) {
    int i = blockIdx.x, t = threadIdx.x;
    float g1 = g_gamma[0], g2 = g_gamma[1];
    const uint4* row = (const uint4*)(D + (size_t)i * N);
    float s = 0.f;
    #pragma unroll 2
    for (int j = t; j < N / 8; j += 256) {
        uint4 v = row[j];
        unsigned words[4] = {v.x, v.y, v.z, v.w};
        #pragma unroll
        for (int w = 0; w < 4; w++) {
            float2 p = __half22float2(*(__half2*)&words[w]);
            float da = p.x + DSHIFT, db = p.y + DSHIFT;
            s += __expf(-g1 * da) + __expf(-g2 * da)
               + __expf(-g1 * db) + __expf(-g2 * db);
        }
    }
    __shared__ float sh[256];
    sh[t] = s;
    __syncthreads();
    #pragma unroll
    for (int k = 128; k > 0; k >>= 1) {
        if (t < k) sh[t] += sh[t + k];
        __syncthreads();
    }
    if (t == 0) g_sim[i] = sh[0] * (1.0f / (float)N);
}

// ---------------------------------------------------------------------------
// 6) final: out[i] = g_sim[i] - mean of valid self partials
// ---------------------------------------------------------------------------
__global__ void self_final_kernel(float* __restrict__ out) {
    int i = blockIdx.x * blockDim.x + threadIdx.x;
    int t = i >> 7;
    const float* rp = g_selfpart  + (size_t)i * 128;
    const float* cp = g_selfpart2 + (size_t)i * 64;
    float s = 0.f;
    for (int b = 4 * t; b < 128; b++) s += rp[b];
    for (int b = 0; b < 2 * t; b++)  s += cp[b];
    out[i] = g_sim[i] - s * (1.0f / (float)N);
}

// ---------------------------------------------------------------------------
// Host orchestration (graph-capturable; d2 branch forked onto 2nd stream)
// ---------------------------------------------------------------------------
extern "C" void kernel_launch(void* const* d_in, const int* in_sizes, int n_in,
                              void* d_out, int out_size) {
    const float* state   = (const float*)d_in[0];
    const float* action  = (const float*)d_in[1];
    const float* estate  = (const float*)d_in[2];
    const float* eaction = (const float*)d_in[3];
    float* out = (float*)d_out;

    // one-time (non-captured first call) stream/event creation
    static cudaStream_t sB = nullptr;
    static cudaEvent_t  evF = nullptr, evJ = nullptr;
    if (!sB) {
        cudaStreamCreateWithFlags(&sB, cudaStreamNonBlocking);
        cudaEventCreateWithFlags(&evF, cudaEventDisableTiming);
        cudaEventCreateWithFlags(&evJ, cudaEventDisableTiming);
    }

    float *p_esa, *p_x2, *p_y2;
    __half *p_D, *p_HA, *p_HB;
    cudaGetSymbolAddress((void**)&p_esa, g_esa);
    cudaGetSymbolAddress((void**)&p_x2,  g_x2);
    cudaGetSymbolAddress((void**)&p_y2,  g_y2);
    cudaGetSymbolAddress((void**)&p_D,   g_D);
    cudaGetSymbolAddress((void**)&p_HA,  g_HA);
    cudaGetSymbolAddress((void**)&p_HB,  g_HB);

    cudaFuncSetAttribute(hmma_dist_gemm<0>,
                         cudaFuncAttributeMaxDynamicSharedMemorySize, GM_SMEM);
    cudaFuncSetAttribute(hmma_dist_gemm<1>,
                         cudaFuncAttributeMaxDynamicSharedMemorySize, GM_SMEM);

    // 1) concat + norms + fp16 copies (also zeroes g_hist2)
    prep_kernel<<<N, 256>>>(state,  action,  nullptr, p_x2, p_HA);
    prep_kernel<<<N, 256>>>(estate, eaction, p_esa,   p_y2, p_HB);

    // fork: branch B (gamma_2 chain) on stream sB
    cudaEventRecord(evF, 0);
    cudaStreamWaitEvent(sB, evF, 0);
    d2_part_kernel<<<dim3(10, NSLAB), 256, 0, sB>>>();
    d2_final_kernel<<<DIM, DIM, 0, sB>>>();
    d2_median_kernel<<<1, 1024, 0, sB>>>();
    cudaEventRecord(evJ, sB);

    // branch A (main stream): GEMM1 + D-median -> gamma_1
    dim3 ggrid(N / 128, N / 128);
    hmma_dist_gemm<0><<<ggrid, 256, GM_SMEM>>>(p_HA, p_HB, p_x2, p_y2, p_D);
    {
        unsigned n8 = ((unsigned)N * (unsigned)N) / 8u;
        select_hist_low<<<2048, 256>>>(p_D, n8);
        select_finalize16<<<1, 256>>>();
    }

    // join: rowsum needs both gammas
    cudaStreamWaitEvent(0, evJ, 0);

    // 5) agent-expert similarity means from stored shifted fp16 D
    rowsum_kernel<<<N, 256>>>(p_D);

    // 6) self-distance GEMM: fp16, triangular, fused row+col sums
    hmma_dist_gemm<1><<<NTRI, 256, GM_SMEM>>>(p_HA, p_HA, p_x2, p_x2, nullptr);
    self_final_kernel<<<N / 256, 256>>>(out);
}